// round 3
// baseline (speedup 1.0000x reference)
#include <cuda_runtime.h>
#include <cuda_bf16.h>

// ---------------------------------------------------------------------------
// Scratch (static device globals — no allocations anywhere)
// ---------------------------------------------------------------------------
__device__ float g_h1[32u * 64u * 16u * 32u * 32u];   // 33,554,432 (134 MB)
__device__ float g_c2[32u * 128u * 8u * 16u * 16u];   //  8,388,608
__device__ float g_c3[32u * 256u * 4u * 8u * 8u];     //  2,097,152
__device__ float g_c4[32u * 512u * 2u * 4u * 4u];     //    524,288
__device__ float g_c4p[4u * 524288u];                 // split-K partials
__device__ float g_bnscale[512];
__device__ float g_bnshift[512];
__device__ float g_d[32 * 32];

// ---------------------------------------------------------------------------
// Layer 1: conv3d (64,1,2,4,4), stride (2,2,2), pad (0,1,1), fused lrelu
// x: (32,1,32,64,64)  ->  h1: (32,64,16,32,32)
// grid (od=16, n=32), block 1024 = (oh,ow)
// ---------------------------------------------------------------------------
__global__ __launch_bounds__(1024, 1)
void conv1_kernel(const float* __restrict__ x, const float* __restrict__ w1)
{
    __shared__ float ws[64 * 32];
    const int t = threadIdx.x;
    for (int i = t; i < 2048; i += 1024) ws[i] = w1[i];
    __syncthreads();

    const int od = blockIdx.x;
    const int n  = blockIdx.y;
    const int oh = t >> 5;
    const int ow = t & 31;

    const float* xb = x + (size_t)n * 131072 + (size_t)(od * 2) * 4096;
    const int ih0 = oh * 2 - 1;
    const int iw0 = ow * 2 - 1;

    float v[32];
#pragma unroll
    for (int kd = 0; kd < 2; ++kd)
#pragma unroll
        for (int kh = 0; kh < 4; ++kh)
#pragma unroll
            for (int kw = 0; kw < 4; ++kw) {
                const int ih = ih0 + kh, iw = iw0 + kw;
                const bool ok = ((unsigned)ih < 64u) && ((unsigned)iw < 64u);
                v[kd * 16 + kh * 4 + kw] = ok ? xb[kd * 4096 + ih * 64 + iw] : 0.f;
            }

    float* outb = g_h1 + ((size_t)(n * 64) * 16 + od) * 1024 + t;
#pragma unroll 4
    for (int c = 0; c < 64; ++c) {
        const float4* wp = (const float4*)&ws[c * 32];
        float acc = 0.f;
#pragma unroll
        for (int q = 0; q < 8; ++q) {
            const float4 w4 = wp[q];
            acc += v[q * 4 + 0] * w4.x + v[q * 4 + 1] * w4.y
                 + v[q * 4 + 2] * w4.z + v[q * 4 + 3] * w4.w;
        }
        acc = (acc >= 0.f) ? acc : 0.2f * acc;
        outb[(size_t)c * 16384] = acc;   // channel stride = 16*1024
    }
}

// ---------------------------------------------------------------------------
// Generic implicit-GEMM conv3d: kernel 4x4x4, stride 2, pad 1 (all dims).
// GEMM view: M = 32*OD*OH*OW (spatial), N = Cout, K = Cin*64.
// Tile: BM=128, BN=128, BK=16, 256 threads, 8x8 micro-tile per thread.
// Optional split-K over blockIdx.z writing to partial slices.
// Output layout NCDHW (raw conv output, no activation).
// ---------------------------------------------------------------------------
__global__ __launch_bounds__(256, 2)
void convg_kernel(const float* __restrict__ in, const float* __restrict__ w,
                  float* __restrict__ out,
                  int Cin, int Cout, int OD, int OH, int OW,
                  int ID, int IH, int IW,
                  int kPerSplit, int sliceElems)
{
    __shared__ __align__(16) float As[16][132];
    __shared__ __align__(16) float Bs[16][132];

    const int t    = threadIdx.x;
    const int OHW  = OH * OW;
    const int ODHW = OD * OHW;
    const int IHW  = IH * IW;
    const int K    = Cin * 64;

    const int mBase = blockIdx.x * 128;
    const int cBase = blockIdx.y * 128;
    const int kBase = blockIdx.z * kPerSplit;

    // ---- loader state (one m row + 8 consecutive k per thread) ----
    const int lm   = t >> 1;           // 0..127
    const int koff = (t & 1) * 8;      // 0 or 8
    const int mload = mBase + lm;
    const int n_l  = mload / ODHW;
    const int s_l  = mload % ODHW;
    const int od_l = s_l / OHW;
    const int r_l  = s_l % OHW;
    const int oh_l = r_l / OW;
    const int ow_l = r_l % OW;
    const int id0  = od_l * 2 - 1;

    int  hw[8];
    bool okhw[8];
#pragma unroll
    for (int i = 0; i < 8; ++i) {
        const int kk = koff + i;
        const int kh = kk >> 2, kw = kk & 3;
        const int ih = oh_l * 2 - 1 + kh;
        const int iw = ow_l * 2 - 1 + kw;
        okhw[i] = ((unsigned)ih < (unsigned)IH) && ((unsigned)iw < (unsigned)IW);
        hw[i]   = ih * IW + iw;
    }
    const float* wrow = w + (size_t)(cBase + lm) * K + kBase + koff;

    const int row0 = (t >> 4) * 8;   // M micro offset
    const int col0 = (t & 15) * 8;   // N micro offset

    float acc[8][8];
#pragma unroll
    for (int a = 0; a < 8; ++a)
#pragma unroll
        for (int b = 0; b < 8; ++b) acc[a][b] = 0.f;

    const int nChunks = kPerSplit >> 4;
    for (int kc = 0; kc < nChunks; ++kc) {
        const int k0  = kBase + (kc << 4);
        const int cin = k0 >> 6;
        const int kd  = (k0 >> 4) & 3;
        const int id  = id0 + kd;
        const bool okd = (unsigned)id < (unsigned)ID;
        const float* ib = in + ((size_t)(n_l * Cin + cin) * ID + id) * IHW;

        float va[8];
#pragma unroll
        for (int i = 0; i < 8; ++i)
            va[i] = (okd && okhw[i]) ? ib[hw[i]] : 0.f;

        const float4 b0 = *(const float4*)(wrow);
        const float4 b1 = *(const float4*)(wrow + 4);
        wrow += 16;

        __syncthreads();   // previous compute done before overwriting tiles
#pragma unroll
        for (int i = 0; i < 8; ++i) As[koff + i][lm] = va[i];
        Bs[koff + 0][lm] = b0.x;  Bs[koff + 1][lm] = b0.y;
        Bs[koff + 2][lm] = b0.z;  Bs[koff + 3][lm] = b0.w;
        Bs[koff + 4][lm] = b1.x;  Bs[koff + 5][lm] = b1.y;
        Bs[koff + 6][lm] = b1.z;  Bs[koff + 7][lm] = b1.w;
        __syncthreads();

#pragma unroll
        for (int kk = 0; kk < 16; ++kk) {
            const float4 a0 = *(const float4*)&As[kk][row0];
            const float4 a1 = *(const float4*)&As[kk][row0 + 4];
            const float4 c0 = *(const float4*)&Bs[kk][col0];
            const float4 c1 = *(const float4*)&Bs[kk][col0 + 4];
            const float ar[8] = {a0.x, a0.y, a0.z, a0.w, a1.x, a1.y, a1.z, a1.w};
            const float br[8] = {c0.x, c0.y, c0.z, c0.w, c1.x, c1.y, c1.z, c1.w};
#pragma unroll
            for (int a = 0; a < 8; ++a)
#pragma unroll
                for (int b = 0; b < 8; ++b)
                    acc[a][b] += ar[a] * br[b];
        }
    }

    // ---- epilogue: write NCDHW (per split slice) ----
    float* outz = out + (size_t)blockIdx.z * sliceElems;
#pragma unroll
    for (int a = 0; a < 8; ++a) {
        const int m   = mBase + row0 + a;
        const int n_o = m / ODHW;
        const int s_o = m % ODHW;
        float* ob = outz + (size_t)(n_o * Cout + cBase + col0) * ODHW + s_o;
#pragma unroll
        for (int b = 0; b < 8; ++b)
            ob[(size_t)b * ODHW] = acc[a][b];
    }
}

// ---------------------------------------------------------------------------
// Sum the 4 split-K partials of conv4 into g_c4.
// ---------------------------------------------------------------------------
__global__ void reduce4_kernel()
{
    const int i = blockIdx.x * 256 + threadIdx.x;   // grid sized to 524288
    g_c4[i] = g_c4p[i] + g_c4p[i + 524288] + g_c4p[i + 2 * 524288]
            + g_c4p[i + 3 * 524288];
}

// ---------------------------------------------------------------------------
// BatchNorm (training mode) statistics: one block per channel.
// Produces scale/shift so that y = x*scale + shift == (x-mean)*rsqrt(var+eps)*g + b
// ---------------------------------------------------------------------------
__global__ void bn_stats_kernel(const float* __restrict__ in,
                                const float* __restrict__ g,
                                const float* __restrict__ b,
                                int C, int ODHW)
{
    const int c = blockIdx.x;
    const int t = threadIdx.x;
    double s = 0.0, s2 = 0.0;
    for (int n = 0; n < 32; ++n) {
        const float* base = in + (size_t)(n * C + c) * ODHW;
        for (int sp = t; sp < ODHW; sp += 256) {
            const double v = (double)base[sp];
            s  += v;
            s2 += v * v;
        }
    }
    __shared__ double sh[256], sh2[256];
    sh[t] = s; sh2[t] = s2;
    __syncthreads();
    for (int o = 128; o > 0; o >>= 1) {
        if (t < o) { sh[t] += sh[t + o]; sh2[t] += sh2[t + o]; }
        __syncthreads();
    }
    if (t == 0) {
        const double cnt  = 32.0 * (double)ODHW;
        const double mean = sh[0] / cnt;
        const double var  = sh2[0] / cnt - mean * mean;
        const double sc   = (double)g[c] / sqrt(var + 1e-5);
        g_bnscale[c] = (float)sc;
        g_bnshift[c] = (float)((double)b[c] - mean * sc);
    }
}

// ---------------------------------------------------------------------------
// In-place BN apply + leaky ReLU.
// ---------------------------------------------------------------------------
__global__ void bn_lrelu_kernel(float* __restrict__ x, int C, int ODHW, int total)
{
    const int i = blockIdx.x * 256 + threadIdx.x;
    if (i >= total) return;
    const int c = (i / ODHW) % C;
    float v = x[i] * g_bnscale[c] + g_bnshift[c];
    x[i] = (v >= 0.f) ? v : 0.2f * v;
}

// ---------------------------------------------------------------------------
// Minibatch discrimination: d[i][j] = mean |hf_i - hf_j| over 16384, +1e6 on diag.
// One block per (i,j).
// ---------------------------------------------------------------------------
__global__ void pairwise_kernel()
{
    const int i = blockIdx.y, j = blockIdx.x, t = threadIdx.x;
    const float* a = g_c4 + (size_t)i * 16384;
    const float* b = g_c4 + (size_t)j * 16384;
    float s = 0.f;
    for (int k = t; k < 16384; k += 256) s += fabsf(a[k] - b[k]);
    __shared__ float sh[256];
    sh[t] = s;
    __syncthreads();
    for (int o = 128; o > 0; o >>= 1) {
        if (t < o) sh[t] += sh[t + o];
        __syncthreads();
    }
    if (t == 0)
        g_d[i * 32 + j] = sh[0] * (1.f / 16384.f) + ((i == j) ? 1e6f : 0.f);
}

// ---------------------------------------------------------------------------
// Final: s[n] = min_j d[n][j]; out[n] = dot(h4[n], w5[0:16384]) + s[n]*sum(w5 tail)
// One block per batch element.
// ---------------------------------------------------------------------------
__global__ void final_kernel(const float* __restrict__ w5, float* __restrict__ out)
{
    const int n = blockIdx.x, t = threadIdx.x;

    __shared__ float shm[256];
    shm[t] = (t < 32) ? g_d[n * 32 + t] : 1e30f;
    __syncthreads();
    for (int o = 128; o > 0; o >>= 1) {
        if (t < o) shm[t] = fminf(shm[t], shm[t + o]);
        __syncthreads();
    }
    const float s = shm[0];
    __syncthreads();

    double acc = 0.0;
    const float* h = g_c4 + (size_t)n * 16384;
    for (int k = t; k < 16384; k += 256)
        acc += (double)h[k] * (double)w5[k];
    if (t < 32)
        acc += (double)s * (double)w5[16384 + t];

    __shared__ double shd[256];
    shd[t] = acc;
    __syncthreads();
    for (int o = 128; o > 0; o >>= 1) {
        if (t < o) shd[t] += shd[t + o];
        __syncthreads();
    }
    if (t == 0) out[n] = (float)shd[0];
}

// ---------------------------------------------------------------------------
// Launch chain (graph-capturable: kernel launches only)
// Inputs (metadata order): x, w1, w2, g2, b2, w3, g3, b3, w4, g4, b4, w5
// ---------------------------------------------------------------------------
extern "C" void kernel_launch(void* const* d_in, const int* in_sizes, int n_in,
                              void* d_out, int out_size)
{
    (void)in_sizes; (void)n_in; (void)out_size;
    const float* x  = (const float*)d_in[0];
    const float* w1 = (const float*)d_in[1];
    const float* w2 = (const float*)d_in[2];
    const float* g2 = (const float*)d_in[3];
    const float* b2 = (const float*)d_in[4];
    const float* w3 = (const float*)d_in[5];
    const float* g3 = (const float*)d_in[6];
    const float* b3 = (const float*)d_in[7];
    const float* w4 = (const float*)d_in[8];
    const float* g4 = (const float*)d_in[9];
    const float* b4 = (const float*)d_in[10];
    const float* w5 = (const float*)d_in[11];
    float* out = (float*)d_out;

    float *h1, *c2, *c3, *c4, *c4p;
    cudaGetSymbolAddress((void**)&h1,  g_h1);
    cudaGetSymbolAddress((void**)&c2,  g_c2);
    cudaGetSymbolAddress((void**)&c3,  g_c3);
    cudaGetSymbolAddress((void**)&c4,  g_c4);
    cudaGetSymbolAddress((void**)&c4p, g_c4p);

    // L1: conv + lrelu
    conv1_kernel<<<dim3(16, 32), 1024>>>(x, w1);

    // L2: conv (M=65536, N=128, K=4096)
    convg_kernel<<<dim3(512, 1, 1), 256>>>(h1, w2, c2,
                                           64, 128, 8, 16, 16, 16, 32, 32,
                                           4096, 0);
    bn_stats_kernel<<<128, 256>>>(c2, g2, b2, 128, 2048);
    bn_lrelu_kernel<<<8388608 / 256, 256>>>(c2, 128, 2048, 8388608);

    // L3: conv (M=8192, N=256, K=8192)
    convg_kernel<<<dim3(64, 2, 1), 256>>>(c2, w3, c3,
                                          128, 256, 4, 8, 8, 8, 16, 16,
                                          8192, 0);
    bn_stats_kernel<<<256, 256>>>(c3, g3, b3, 256, 256);
    bn_lrelu_kernel<<<2097152 / 256, 256>>>(c3, 256, 256, 2097152);

    // L4: conv (M=1024, N=512, K=16384) with split-K = 4 for parallelism
    convg_kernel<<<dim3(8, 4, 4), 256>>>(c3, w4, c4p,
                                         256, 512, 2, 4, 4, 4, 8, 8,
                                         4096, 524288);
    reduce4_kernel<<<524288 / 256, 256>>>();
    bn_stats_kernel<<<512, 256>>>(c4, g4, b4, 512, 32);
    bn_lrelu_kernel<<<524288 / 256, 256>>>(c4, 512, 32, 524288);

    // Minibatch discrimination + final conv
    pairwise_kernel<<<dim3(32, 32), 256>>>();
    final_kernel<<<32, 256>>>(w5, out);
}

// round 4
// speedup vs baseline: 1.0635x; 1.0635x over previous
#include <cuda_runtime.h>
#include <cuda_bf16.h>

// ---------------------------------------------------------------------------
// Scratch (static device globals — no allocations anywhere)
// ---------------------------------------------------------------------------
__device__ float g_h1[32u * 64u * 16u * 32u * 32u];   // 33,554,432 (134 MB)
__device__ float g_c2[32u * 128u * 8u * 16u * 16u];   //  8,388,608
__device__ float g_c3[32u * 256u * 4u * 8u * 8u];     //  2,097,152
__device__ float g_c3p[2u * 2097152u];                // conv3 split-K partials
__device__ float g_c4[32u * 512u * 2u * 4u * 4u];     //    524,288
__device__ float g_c4p[4u * 524288u];                 // conv4 split-K partials
__device__ float g_bnscale[512];
__device__ float g_bnshift[512];
__device__ float g_d[32 * 32];

// ---------------------------------------------------------------------------
// Packed fp32x2 helpers (Blackwell sm_100a: SASS FFMA2, PTX-only path)
// ---------------------------------------------------------------------------
__device__ __forceinline__ unsigned long long bcast2(float v)
{
    unsigned int u = __float_as_uint(v);
    unsigned long long r;
    asm("mov.b64 %0, {%1, %1};" : "=l"(r) : "r"(u));
    return r;
}

__device__ __forceinline__ void fma2(unsigned long long& d,
                                     unsigned long long a,
                                     unsigned long long b)
{
    asm("fma.rn.f32x2 %0, %1, %2, %0;" : "+l"(d) : "l"(a), "l"(b));
}

__device__ __forceinline__ void unpack2(unsigned long long v, float& lo, float& hi)
{
    unsigned int ulo, uhi;
    asm("mov.b64 {%0, %1}, %2;" : "=r"(ulo), "=r"(uhi) : "l"(v));
    lo = __uint_as_float(ulo);
    hi = __uint_as_float(uhi);
}

// ---------------------------------------------------------------------------
// Layer 1: conv3d (64,1,2,4,4), stride (2,2,2), pad (0,1,1), fused lrelu
// x: (32,1,32,64,64)  ->  h1: (32,64,16,32,32)
// grid (od=16, n=32), block 1024 = (oh,ow)
// ---------------------------------------------------------------------------
__global__ __launch_bounds__(1024, 1)
void conv1_kernel(const float* __restrict__ x, const float* __restrict__ w1)
{
    __shared__ float ws[64 * 32];
    const int t = threadIdx.x;
    for (int i = t; i < 2048; i += 1024) ws[i] = w1[i];
    __syncthreads();

    const int od = blockIdx.x;
    const int n  = blockIdx.y;
    const int oh = t >> 5;
    const int ow = t & 31;

    const float* xb = x + (size_t)n * 131072 + (size_t)(od * 2) * 4096;
    const int ih0 = oh * 2 - 1;
    const int iw0 = ow * 2 - 1;

    float v[32];
#pragma unroll
    for (int kd = 0; kd < 2; ++kd)
#pragma unroll
        for (int kh = 0; kh < 4; ++kh)
#pragma unroll
            for (int kw = 0; kw < 4; ++kw) {
                const int ih = ih0 + kh, iw = iw0 + kw;
                const bool ok = ((unsigned)ih < 64u) && ((unsigned)iw < 64u);
                v[kd * 16 + kh * 4 + kw] = ok ? xb[kd * 4096 + ih * 64 + iw] : 0.f;
            }

    float* outb = g_h1 + ((size_t)(n * 64) * 16 + od) * 1024 + t;
#pragma unroll 4
    for (int c = 0; c < 64; ++c) {
        const float4* wp = (const float4*)&ws[c * 32];
        float acc = 0.f;
#pragma unroll
        for (int q = 0; q < 8; ++q) {
            const float4 w4 = wp[q];
            acc += v[q * 4 + 0] * w4.x + v[q * 4 + 1] * w4.y
                 + v[q * 4 + 2] * w4.z + v[q * 4 + 3] * w4.w;
        }
        acc = (acc >= 0.f) ? acc : 0.2f * acc;
        outb[(size_t)c * 16384] = acc;   // channel stride = 16*1024
    }
}

// ---------------------------------------------------------------------------
// Generic implicit-GEMM conv3d: kernel 4x4x4, stride 2, pad 1 (all dims).
// GEMM view: M = 32*OD*OH*OW (spatial), N = Cout, K = Cin*64.
// Tile: BM=128, BN=128, BK=16, 256 threads, 8x8 micro-tile per thread,
// accumulators packed pairwise along M and fed to fma.rn.f32x2 (FFMA2).
// Optional split-K over blockIdx.z writing to partial slices.
// ---------------------------------------------------------------------------
__global__ __launch_bounds__(256, 2)
void convg_kernel(const float* __restrict__ in, const float* __restrict__ w,
                  float* __restrict__ out,
                  int Cin, int Cout, int OD, int OH, int OW,
                  int ID, int IH, int IW,
                  int kPerSplit, int sliceElems)
{
    __shared__ __align__(16) float As[16][132];
    __shared__ __align__(16) float Bs[16][132];

    const int t    = threadIdx.x;
    const int OHW  = OH * OW;
    const int ODHW = OD * OHW;
    const int IHW  = IH * IW;
    const int K    = Cin * 64;

    const int mBase = blockIdx.x * 128;
    const int cBase = blockIdx.y * 128;
    const int kBase = blockIdx.z * kPerSplit;

    // ---- loader state (one m row + 8 consecutive k per thread) ----
    const int lm   = t >> 1;           // 0..127
    const int koff = (t & 1) * 8;      // 0 or 8
    const int mload = mBase + lm;
    const int n_l  = mload / ODHW;
    const int s_l  = mload % ODHW;
    const int od_l = s_l / OHW;
    const int r_l  = s_l % OHW;
    const int oh_l = r_l / OW;
    const int ow_l = r_l % OW;
    const int id0  = od_l * 2 - 1;

    int  hw[8];
    bool okhw[8];
#pragma unroll
    for (int i = 0; i < 8; ++i) {
        const int kk = koff + i;
        const int kh = kk >> 2, kw = kk & 3;
        const int ih = oh_l * 2 - 1 + kh;
        const int iw = ow_l * 2 - 1 + kw;
        okhw[i] = ((unsigned)ih < (unsigned)IH) && ((unsigned)iw < (unsigned)IW);
        hw[i]   = ih * IW + iw;
    }
    const float* wrow = w + (size_t)(cBase + lm) * K + kBase + koff;

    const int row0 = (t >> 4) * 8;   // M micro offset
    const int col0 = (t & 15) * 8;   // N micro offset

    // packed accumulators: acc2[i][j] holds rows (row0+2i, row0+2i+1), col j
    unsigned long long acc2[4][8];
#pragma unroll
    for (int a = 0; a < 4; ++a)
#pragma unroll
        for (int b = 0; b < 8; ++b) acc2[a][b] = 0ull;

    const int nChunks = kPerSplit >> 4;
    for (int kc = 0; kc < nChunks; ++kc) {
        const int k0  = kBase + (kc << 4);
        const int cin = k0 >> 6;
        const int kd  = (k0 >> 4) & 3;
        const int id  = id0 + kd;
        const bool okd = (unsigned)id < (unsigned)ID;
        const float* ib = in + ((size_t)(n_l * Cin + cin) * ID + id) * IHW;

        float va[8];
#pragma unroll
        for (int i = 0; i < 8; ++i)
            va[i] = (okd && okhw[i]) ? ib[hw[i]] : 0.f;

        const float4 b0 = *(const float4*)(wrow);
        const float4 b1 = *(const float4*)(wrow + 4);
        wrow += 16;

        __syncthreads();   // previous compute done before overwriting tiles
#pragma unroll
        for (int i = 0; i < 8; ++i) As[koff + i][lm] = va[i];
        Bs[koff + 0][lm] = b0.x;  Bs[koff + 1][lm] = b0.y;
        Bs[koff + 2][lm] = b0.z;  Bs[koff + 3][lm] = b0.w;
        Bs[koff + 4][lm] = b1.x;  Bs[koff + 5][lm] = b1.y;
        Bs[koff + 6][lm] = b1.z;  Bs[koff + 7][lm] = b1.w;
        __syncthreads();

#pragma unroll
        for (int kk = 0; kk < 16; ++kk) {
            // A pairs along M: direct 64-bit reads (As row is 16B-aligned:
            // 132 floats = 33*16B per row, row0 multiple of 8 floats)
            const ulonglong2* ap = (const ulonglong2*)&As[kk][row0];
            const ulonglong2 A01 = ap[0];
            const ulonglong2 A23 = ap[1];
            unsigned long long aa[4] = {A01.x, A01.y, A23.x, A23.y};

            const float4 c0 = *(const float4*)&Bs[kk][col0];
            const float4 c1 = *(const float4*)&Bs[kk][col0 + 4];
            unsigned long long bb[8];
            bb[0] = bcast2(c0.x); bb[1] = bcast2(c0.y);
            bb[2] = bcast2(c0.z); bb[3] = bcast2(c0.w);
            bb[4] = bcast2(c1.x); bb[5] = bcast2(c1.y);
            bb[6] = bcast2(c1.z); bb[7] = bcast2(c1.w);

#pragma unroll
            for (int a = 0; a < 4; ++a)
#pragma unroll
                for (int b = 0; b < 8; ++b)
                    fma2(acc2[a][b], aa[a], bb[b]);
        }
    }

    // ---- unpack + epilogue: write NCDHW (per split slice) ----
    float accf[8][8];
#pragma unroll
    for (int a = 0; a < 4; ++a)
#pragma unroll
        for (int b = 0; b < 8; ++b)
            unpack2(acc2[a][b], accf[2 * a][b], accf[2 * a + 1][b]);

    float* outz = out + (size_t)blockIdx.z * sliceElems;
#pragma unroll
    for (int a = 0; a < 8; ++a) {
        const int m   = mBase + row0 + a;
        const int n_o = m / ODHW;
        const int s_o = m % ODHW;
        float* ob = outz + (size_t)(n_o * Cout + cBase + col0) * ODHW + s_o;
#pragma unroll
        for (int b = 0; b < 8; ++b)
            ob[(size_t)b * ODHW] = accf[a][b];
    }
}

// ---------------------------------------------------------------------------
// Split-K reductions.
// ---------------------------------------------------------------------------
__global__ void reduce4_kernel()
{
    const int i = blockIdx.x * 256 + threadIdx.x;   // grid sized to 524288
    g_c4[i] = g_c4p[i] + g_c4p[i + 524288] + g_c4p[i + 2 * 524288]
            + g_c4p[i + 3 * 524288];
}

__global__ void reduce3_kernel()
{
    const int i = blockIdx.x * 256 + threadIdx.x;   // grid sized to 2097152
    g_c3[i] = g_c3p[i] + g_c3p[i + 2097152];
}

// ---------------------------------------------------------------------------
// BatchNorm (training mode) statistics: one block per channel.
// ---------------------------------------------------------------------------
__global__ void bn_stats_kernel(const float* __restrict__ in,
                                const float* __restrict__ g,
                                const float* __restrict__ b,
                                int C, int ODHW)
{
    const int c = blockIdx.x;
    const int t = threadIdx.x;
    double s = 0.0, s2 = 0.0;
    for (int n = 0; n < 32; ++n) {
        const float* base = in + (size_t)(n * C + c) * ODHW;
        for (int sp = t; sp < ODHW; sp += 256) {
            const double v = (double)base[sp];
            s  += v;
            s2 += v * v;
        }
    }
    __shared__ double sh[256], sh2[256];
    sh[t] = s; sh2[t] = s2;
    __syncthreads();
    for (int o = 128; o > 0; o >>= 1) {
        if (t < o) { sh[t] += sh[t + o]; sh2[t] += sh2[t + o]; }
        __syncthreads();
    }
    if (t == 0) {
        const double cnt  = 32.0 * (double)ODHW;
        const double mean = sh[0] / cnt;
        const double var  = sh2[0] / cnt - mean * mean;
        const double sc   = (double)g[c] / sqrt(var + 1e-5);
        g_bnscale[c] = (float)sc;
        g_bnshift[c] = (float)((double)b[c] - mean * sc);
    }
}

// ---------------------------------------------------------------------------
// In-place BN apply + leaky ReLU (vectorized float4; ODHW always %4==0).
// ---------------------------------------------------------------------------
__global__ void bn_lrelu_kernel(float4* __restrict__ x, int C, int ODHW4, int total4)
{
    const int i = blockIdx.x * 256 + threadIdx.x;
    if (i >= total4) return;
    const int c = (i / ODHW4) % C;
    const float sc = g_bnscale[c], sh = g_bnshift[c];
    float4 v = x[i];
    v.x = v.x * sc + sh;  v.x = (v.x >= 0.f) ? v.x : 0.2f * v.x;
    v.y = v.y * sc + sh;  v.y = (v.y >= 0.f) ? v.y : 0.2f * v.y;
    v.z = v.z * sc + sh;  v.z = (v.z >= 0.f) ? v.z : 0.2f * v.z;
    v.w = v.w * sc + sh;  v.w = (v.w >= 0.f) ? v.w : 0.2f * v.w;
    x[i] = v;
}

// ---------------------------------------------------------------------------
// Minibatch discrimination: d[i][j] = mean |hf_i - hf_j| over 16384, +1e6 diag.
// ---------------------------------------------------------------------------
__global__ void pairwise_kernel()
{
    const int i = blockIdx.y, j = blockIdx.x, t = threadIdx.x;
    const float* a = g_c4 + (size_t)i * 16384;
    const float* b = g_c4 + (size_t)j * 16384;
    float s = 0.f;
    for (int k = t; k < 16384; k += 256) s += fabsf(a[k] - b[k]);
    __shared__ float sh[256];
    sh[t] = s;
    __syncthreads();
    for (int o = 128; o > 0; o >>= 1) {
        if (t < o) sh[t] += sh[t + o];
        __syncthreads();
    }
    if (t == 0)
        g_d[i * 32 + j] = sh[0] * (1.f / 16384.f) + ((i == j) ? 1e6f : 0.f);
}

// ---------------------------------------------------------------------------
// Final: s[n] = min_j d[n][j]; out[n] = dot(h4[n], w5[0:16384]) + s[n]*w5tail
// ---------------------------------------------------------------------------
__global__ void final_kernel(const float* __restrict__ w5, float* __restrict__ out)
{
    const int n = blockIdx.x, t = threadIdx.x;

    __shared__ float shm[256];
    shm[t] = (t < 32) ? g_d[n * 32 + t] : 1e30f;
    __syncthreads();
    for (int o = 128; o > 0; o >>= 1) {
        if (t < o) shm[t] = fminf(shm[t], shm[t + o]);
        __syncthreads();
    }
    const float s = shm[0];
    __syncthreads();

    double acc = 0.0;
    const float* h = g_c4 + (size_t)n * 16384;
    for (int k = t; k < 16384; k += 256)
        acc += (double)h[k] * (double)w5[k];
    if (t < 32)
        acc += (double)s * (double)w5[16384 + t];

    __shared__ double shd[256];
    shd[t] = acc;
    __syncthreads();
    for (int o = 128; o > 0; o >>= 1) {
        if (t < o) shd[t] += shd[t + o];
        __syncthreads();
    }
    if (t == 0) out[n] = (float)shd[0];
}

// ---------------------------------------------------------------------------
// Launch chain (graph-capturable: kernel launches only)
// Inputs (metadata order): x, w1, w2, g2, b2, w3, g3, b3, w4, g4, b4, w5
// ---------------------------------------------------------------------------
extern "C" void kernel_launch(void* const* d_in, const int* in_sizes, int n_in,
                              void* d_out, int out_size)
{
    (void)in_sizes; (void)n_in; (void)out_size;
    const float* x  = (const float*)d_in[0];
    const float* w1 = (const float*)d_in[1];
    const float* w2 = (const float*)d_in[2];
    const float* g2 = (const float*)d_in[3];
    const float* b2 = (const float*)d_in[4];
    const float* w3 = (const float*)d_in[5];
    const float* g3 = (const float*)d_in[6];
    const float* b3 = (const float*)d_in[7];
    const float* w4 = (const float*)d_in[8];
    const float* g4 = (const float*)d_in[9];
    const float* b4 = (const float*)d_in[10];
    const float* w5 = (const float*)d_in[11];
    float* out = (float*)d_out;

    float *h1, *c2, *c3, *c3p, *c4, *c4p;
    cudaGetSymbolAddress((void**)&h1,  g_h1);
    cudaGetSymbolAddress((void**)&c2,  g_c2);
    cudaGetSymbolAddress((void**)&c3,  g_c3);
    cudaGetSymbolAddress((void**)&c3p, g_c3p);
    cudaGetSymbolAddress((void**)&c4,  g_c4);
    cudaGetSymbolAddress((void**)&c4p, g_c4p);

    // L1: conv + lrelu
    conv1_kernel<<<dim3(16, 32), 1024>>>(x, w1);

    // L2: conv (M=65536, N=128, K=4096)
    convg_kernel<<<dim3(512, 1, 1), 256>>>(h1, w2, c2,
                                           64, 128, 8, 16, 16, 16, 32, 32,
                                           4096, 0);
    bn_stats_kernel<<<128, 256>>>(c2, g2, b2, 128, 2048);
    bn_lrelu_kernel<<<(8388608 / 4) / 256, 256>>>((float4*)c2, 128, 512, 2097152);

    // L3: conv (M=8192, N=256, K=8192), split-K=2 to fill the chip
    convg_kernel<<<dim3(64, 2, 2), 256>>>(c2, w3, c3p,
                                          128, 256, 4, 8, 8, 8, 16, 16,
                                          4096, 2097152);
    reduce3_kernel<<<2097152 / 256, 256>>>();
    bn_stats_kernel<<<256, 256>>>(c3, g3, b3, 256, 256);
    bn_lrelu_kernel<<<(2097152 / 4) / 256, 256>>>((float4*)c3, 256, 64, 524288);

    // L4: conv (M=1024, N=512, K=16384), split-K=4
    convg_kernel<<<dim3(8, 4, 4), 256>>>(c3, w4, c4p,
                                         256, 512, 2, 4, 4, 4, 8, 8,
                                         4096, 524288);
    reduce4_kernel<<<524288 / 256, 256>>>();
    bn_stats_kernel<<<512, 256>>>(c4, g4, b4, 512, 32);
    bn_lrelu_kernel<<<(524288 / 4) / 256, 256>>>((float4*)c4, 512, 8, 131072);

    // Minibatch discrimination + final conv
    pairwise_kernel<<<dim3(32, 32), 256>>>();
    final_kernel<<<32, 256>>>(w5, out);
}

// round 7
// speedup vs baseline: 2.1734x; 2.0437x over previous
#include <cuda_runtime.h>
#include <cuda_bf16.h>
#include <cstdint>

#define DEVFN __device__ __forceinline__

// ---------------------------------------------------------------------------
// Scratch (static device globals — no allocations anywhere)
// ---------------------------------------------------------------------------
__device__ unsigned g_h1p[33554432u];        // conv1 out, packed (bf16hi<<16|bf16lo)
__device__ float    g_c2 [8388608u];         // conv2 raw out (fp32, pre-BN)
__device__ unsigned g_c2a[8388608u];         // conv2 activated, packed
__device__ float    g_c3 [2097152u];
__device__ float    g_c3p[2u * 2097152u];    // conv3 split-K partials
__device__ unsigned g_c3a[2097152u];
__device__ float    g_c4 [524288u];
__device__ float    g_c4p[4u * 524288u];     // conv4 split-K partials
__device__ unsigned g_w2p[524288u];          // packed weights
__device__ unsigned g_w3p[2097152u];
__device__ unsigned g_w4p[8388608u];
__device__ float    g_bnscale[512];
__device__ float    g_bnshift[512];
__device__ float    g_d[32 * 32];

// ---------------------------------------------------------------------------
// Helpers
// ---------------------------------------------------------------------------
DEVFN unsigned packhl(float v)
{
    __nv_bfloat16 h = __float2bfloat16(v);
    float r = v - __bfloat162float(h);
    __nv_bfloat16 l = __float2bfloat16(r);
    return ((unsigned)__bfloat16_as_ushort(h) << 16) |
           (unsigned)__bfloat16_as_ushort(l);
}

DEVFN uint32_t smem_u32(const void* p)
{
    uint32_t a;
    asm("{ .reg .u64 t; cvta.to.shared.u64 t, %1; cvt.u32.u64 %0, t; }"
        : "=r"(a) : "l"(p));
    return a;
}

DEVFN void ldsm4(uint32_t* r, uint32_t addr)
{
    asm volatile("ldmatrix.sync.aligned.m8n8.x4.shared.b16 {%0,%1,%2,%3}, [%4];"
                 : "=r"(r[0]), "=r"(r[1]), "=r"(r[2]), "=r"(r[3]) : "r"(addr));
}

DEVFN void mma16816(float* c, const uint32_t* a, uint32_t b0, uint32_t b1)
{
    asm volatile(
        "mma.sync.aligned.m16n8k16.row.col.f32.bf16.bf16.f32 "
        "{%0,%1,%2,%3}, {%4,%5,%6,%7}, {%8,%9}, {%0,%1,%2,%3};"
        : "+f"(c[0]), "+f"(c[1]), "+f"(c[2]), "+f"(c[3])
        : "r"(a[0]), "r"(a[1]), "r"(a[2]), "r"(a[3]), "r"(b0), "r"(b1));
}

// ---------------------------------------------------------------------------
// Weight packer: fp32 -> (bf16hi<<16 | bf16lo)
// ---------------------------------------------------------------------------
__global__ void packw_kernel(const float* __restrict__ w, unsigned* __restrict__ o, int n)
{
    const int i = blockIdx.x * 256 + threadIdx.x;
    if (i < n) o[i] = packhl(w[i]);
}

// ---------------------------------------------------------------------------
// Layer 1: conv3d (64,1,2,4,4), stride (2,2,2), pad (0,1,1), fused lrelu.
// Writes packed hi/lo bf16 u32 directly.
// ---------------------------------------------------------------------------
__global__ __launch_bounds__(1024, 1)
void conv1_kernel(const float* __restrict__ x, const float* __restrict__ w1)
{
    __shared__ float ws[64 * 32];
    const int t = threadIdx.x;
    for (int i = t; i < 2048; i += 1024) ws[i] = w1[i];
    __syncthreads();

    const int od = blockIdx.x;
    const int n  = blockIdx.y;
    const int oh = t >> 5;
    const int ow = t & 31;

    const float* xb = x + (size_t)n * 131072 + (size_t)(od * 2) * 4096;
    const int ih0 = oh * 2 - 1;
    const int iw0 = ow * 2 - 1;

    float v[32];
#pragma unroll
    for (int kd = 0; kd < 2; ++kd)
#pragma unroll
        for (int kh = 0; kh < 4; ++kh)
#pragma unroll
            for (int kw = 0; kw < 4; ++kw) {
                const int ih = ih0 + kh, iw = iw0 + kw;
                const bool ok = ((unsigned)ih < 64u) && ((unsigned)iw < 64u);
                v[kd * 16 + kh * 4 + kw] = ok ? xb[kd * 4096 + ih * 64 + iw] : 0.f;
            }

    unsigned* outb = g_h1p + ((size_t)(n * 64) * 16 + od) * 1024 + t;
#pragma unroll 4
    for (int c = 0; c < 64; ++c) {
        const float4* wp = (const float4*)&ws[c * 32];
        float acc = 0.f;
#pragma unroll
        for (int q = 0; q < 8; ++q) {
            const float4 w4 = wp[q];
            acc += v[q * 4 + 0] * w4.x + v[q * 4 + 1] * w4.y
                 + v[q * 4 + 2] * w4.z + v[q * 4 + 3] * w4.w;
        }
        acc = (acc >= 0.f) ? acc : 0.2f * acc;
        outb[(size_t)c * 16384] = packhl(acc);
    }
}

// ---------------------------------------------------------------------------
// mma.sync bf16 implicit-GEMM conv3d: kernel 4x4x4, stride 2, pad 1.
// D[M=32*ODHW, N=Cout] = A[M,K] * B[N,K]^T, K = Cin*64, hi/lo 3-term split.
// CTA 128x128, 8 warps (4x2), warp tile 32x64, K-chunk 32.
// Smem tiles row-major [row][k] padded to 40 bf16/row (conflict-free ldmatrix).
// ---------------------------------------------------------------------------
#define PADK 40

__global__ __launch_bounds__(256, 1)
void convmma_kernel(const unsigned* __restrict__ inp, const unsigned* __restrict__ wp,
                    float* __restrict__ out,
                    int Cin, int Cout, int OD, int OH, int OW,
                    int ID, int IH, int IW,
                    int kPerSplit, int sliceElems)
{
    __shared__ __align__(16) __nv_bfloat16 sAh[128 * PADK];
    __shared__ __align__(16) __nv_bfloat16 sAl[128 * PADK];
    __shared__ __align__(16) __nv_bfloat16 sBh[128 * PADK];
    __shared__ __align__(16) __nv_bfloat16 sBl[128 * PADK];

    const int t    = threadIdx.x;
    const int lane = t & 31;
    const int wid  = t >> 5;
    const int mw   = (wid & 3) * 32;    // warp M offset in CTA tile
    const int nw   = (wid >> 2) * 64;   // warp N offset

    const int OHW  = OH * OW;
    const int ODHW = OD * OHW;
    const int IHW  = IH * IW;
    const int K    = Cin * 64;

    const int mBase = blockIdx.x * 128;
    const int cBase = blockIdx.y * 128;
    const int kBase = blockIdx.z * kPerSplit;

    // ---- loader state: thread = (row lm, 16-k half) ----
    const int lm   = t >> 1;
    const int khf  = t & 1;              // which 16 of the 32-k chunk
    const int mload = mBase + lm;
    const int n_l = mload / ODHW;
    int srem = mload % ODHW;
    const int od = srem / OHW; srem %= OHW;
    const int oh = srem / OW;
    const int ow = srem % OW;
    const int id0 = od * 2 - 1;

    int hw16[16];
    unsigned okmask = 0;
#pragma unroll
    for (int j = 0; j < 16; ++j) {
        const int kh = j >> 2, kw = j & 3;
        const int ih = oh * 2 - 1 + kh;
        const int iw = ow * 2 - 1 + kw;
        const bool ok = ((unsigned)ih < (unsigned)IH) && ((unsigned)iw < (unsigned)IW);
        hw16[j] = ih * IW + iw;
        okmask |= (unsigned)ok << j;
    }

    const uint32_t aBase = smem_u32(sAh);
    const uint32_t alB   = smem_u32(sAl);
    const uint32_t bBase = smem_u32(sBh);
    const uint32_t blB   = smem_u32(sBl);
    const uint32_t stRow = (uint32_t)(lm * (PADK * 2) + khf * 32);  // byte offset

    float acc[2][8][4];
#pragma unroll
    for (int a = 0; a < 2; ++a)
#pragma unroll
        for (int b = 0; b < 8; ++b)
#pragma unroll
            for (int q = 0; q < 4; ++q) acc[a][b][q] = 0.f;

    const int nCh = kPerSplit >> 5;      // 32-k chunks

    // ---- gather one chunk into registers ----
    unsigned va[16];
    uint4    wbv[4];
    auto gather = [&](int kc) {
        const int k0  = kBase + (kc << 5);
        const int cin = k0 >> 6;
        const int kd  = ((k0 >> 4) & 3) + khf;
        const int id  = id0 + kd;
        const bool okd = (unsigned)id < (unsigned)ID;
        const unsigned* bd = inp + (size_t)(n_l * Cin + cin) * ID * IHW
                           + (size_t)(okd ? id : 0) * IHW;
#pragma unroll
        for (int j = 0; j < 16; ++j)
            va[j] = (okd && ((okmask >> j) & 1)) ? bd[hw16[j]] : 0u;
        const uint4* wq = (const uint4*)(wp + (size_t)(cBase + lm) * K + k0 + khf * 16);
#pragma unroll
        for (int q = 0; q < 4; ++q) wbv[q] = wq[q];
    };

    gather(0);

    for (int kc = 0; kc < nCh; ++kc) {
        __syncthreads();   // previous compute done reading smem

        // ---- hi/lo split + store ----
        const unsigned* wbu = (const unsigned*)wbv;
#pragma unroll
        for (int h = 0; h < 2; ++h) {
            uint4 ha, la, hb, lb;
            unsigned* hap = (unsigned*)&ha; unsigned* lap = (unsigned*)&la;
            unsigned* hbp = (unsigned*)&hb; unsigned* lbp = (unsigned*)&lb;
#pragma unroll
            for (int e = 0; e < 4; ++e) {
                const unsigned a0 = va[h * 8 + e * 2], a1 = va[h * 8 + e * 2 + 1];
                hap[e] = __byte_perm(a0, a1, 0x7632);
                lap[e] = __byte_perm(a0, a1, 0x5410);
                const unsigned b0 = wbu[h * 8 + e * 2], b1 = wbu[h * 8 + e * 2 + 1];
                hbp[e] = __byte_perm(b0, b1, 0x7632);
                lbp[e] = __byte_perm(b0, b1, 0x5410);
            }
            const uint32_t off = stRow + h * 16;
            *(uint4*)((char*)sAh + off) = ha;
            *(uint4*)((char*)sAl + off) = la;
            *(uint4*)((char*)sBh + off) = hb;
            *(uint4*)((char*)sBl + off) = lb;
        }
        __syncthreads();

        if (kc + 1 < nCh) gather(kc + 1);   // prefetch next chunk (global loads)

        // ---- compute: 2 k-steps of 16 ----
#pragma unroll
        for (int ks = 0; ks < 2; ++ks) {
            const uint32_t kq = ks * 16;
            const uint32_t colb = (kq + 8 * (lane >> 4)) * 2;

            uint32_t ah[2][4], al[2][4];
#pragma unroll
            for (int tm = 0; tm < 2; ++tm) {
                const uint32_t ro = (uint32_t)(mw + tm * 16 + (lane & 15)) * (PADK * 2) + colb;
                ldsm4(ah[tm], aBase + ro);
                ldsm4(al[tm], alB + ro);
            }
            uint32_t bh[4][4], bl[4][4];
#pragma unroll
            for (int tp = 0; tp < 4; ++tp) {
                const uint32_t ro = (uint32_t)(nw + tp * 16 + (lane & 15)) * (PADK * 2) + colb;
                ldsm4(bh[tp], bBase + ro);
                ldsm4(bl[tp], blB + ro);
            }
#pragma unroll
            for (int tm = 0; tm < 2; ++tm)
#pragma unroll
                for (int tn = 0; tn < 8; ++tn) {
                    const int tp = tn >> 1, o = tn & 1;
                    mma16816(acc[tm][tn], ah[tm], bh[tp][o], bh[tp][o + 2]);
                    mma16816(acc[tm][tn], ah[tm], bl[tp][o], bl[tp][o + 2]);
                    mma16816(acc[tm][tn], al[tm], bh[tp][o], bh[tp][o + 2]);
                }
        }
    }

    // ---- epilogue: fp32 NCDHW (per split slice) ----
    float* outz = out + (size_t)blockIdx.z * sliceElems;
#pragma unroll
    for (int tm = 0; tm < 2; ++tm) {
        const int m0 = mBase + mw + tm * 16 + (lane >> 2);
#pragma unroll
        for (int half = 0; half < 2; ++half) {
            const int m   = m0 + 8 * half;
            const int n_o = m / ODHW;
            const int s_o = m % ODHW;
            float* ob = outz + (size_t)(n_o * Cout + cBase) * ODHW + s_o;
#pragma unroll
            for (int tn = 0; tn < 8; ++tn) {
                const int col = nw + tn * 8 + 2 * (lane & 3);
                ob[(size_t)col * ODHW]       = acc[tm][tn][half * 2 + 0];
                ob[(size_t)(col + 1) * ODHW] = acc[tm][tn][half * 2 + 1];
            }
        }
    }
}

// ---------------------------------------------------------------------------
// Split-K reductions.
// ---------------------------------------------------------------------------
__global__ void reduce4_kernel()
{
    const int i = blockIdx.x * 256 + threadIdx.x;
    g_c4[i] = g_c4p[i] + g_c4p[i + 524288] + g_c4p[i + 2 * 524288]
            + g_c4p[i + 3 * 524288];
}

__global__ void reduce3_kernel()
{
    const int i = blockIdx.x * 256 + threadIdx.x;
    g_c3[i] = g_c3p[i] + g_c3p[i + 2097152];
}

// ---------------------------------------------------------------------------
// BatchNorm (training mode) statistics.
// ---------------------------------------------------------------------------
__global__ void bn_stats_kernel(const float* __restrict__ in,
                                const float* __restrict__ g,
                                const float* __restrict__ b,
                                int C, int ODHW)
{
    const int c = blockIdx.x;
    const int t = threadIdx.x;
    double s = 0.0, s2 = 0.0;
    for (int n = 0; n < 32; ++n) {
        const float* base = in + (size_t)(n * C + c) * ODHW;
        for (int sp = t; sp < ODHW; sp += 256) {
            const double v = (double)base[sp];
            s += v; s2 += v * v;
        }
    }
    __shared__ double sh[256], sh2[256];
    sh[t] = s; sh2[t] = s2;
    __syncthreads();
    for (int o = 128; o > 0; o >>= 1) {
        if (t < o) { sh[t] += sh[t + o]; sh2[t] += sh2[t + o]; }
        __syncthreads();
    }
    if (t == 0) {
        const double cnt  = 32.0 * (double)ODHW;
        const double mean = sh[0] / cnt;
        const double var  = sh2[0] / cnt - mean * mean;
        const double sc   = (double)g[c] / sqrt(var + 1e-5);
        g_bnscale[c] = (float)sc;
        g_bnshift[c] = (float)((double)b[c] - mean * sc);
    }
}

// ---------------------------------------------------------------------------
// BN apply + lrelu -> packed hi/lo u32 (for next conv's A).
// ---------------------------------------------------------------------------
__global__ void bn_pack_kernel(const float4* __restrict__ in, uint4* __restrict__ op,
                               int C, int ODHW4, int total4)
{
    const int i = blockIdx.x * 256 + threadIdx.x;
    if (i >= total4) return;
    const int c = (i / ODHW4) % C;
    const float sc = g_bnscale[c], sh = g_bnshift[c];
    float4 v = in[i];
    v.x = v.x * sc + sh; v.x = (v.x >= 0.f) ? v.x : 0.2f * v.x;
    v.y = v.y * sc + sh; v.y = (v.y >= 0.f) ? v.y : 0.2f * v.y;
    v.z = v.z * sc + sh; v.z = (v.z >= 0.f) ? v.z : 0.2f * v.z;
    v.w = v.w * sc + sh; v.w = (v.w >= 0.f) ? v.w : 0.2f * v.w;
    uint4 o;
    o.x = packhl(v.x); o.y = packhl(v.y); o.z = packhl(v.z); o.w = packhl(v.w);
    op[i] = o;
}

// ---------------------------------------------------------------------------
// BN apply + lrelu in place (fp32, conv4 output).
// ---------------------------------------------------------------------------
__global__ void bn_lrelu_kernel(float4* __restrict__ x, int C, int ODHW4, int total4)
{
    const int i = blockIdx.x * 256 + threadIdx.x;
    if (i >= total4) return;
    const int c = (i / ODHW4) % C;
    const float sc = g_bnscale[c], sh = g_bnshift[c];
    float4 v = x[i];
    v.x = v.x * sc + sh; v.x = (v.x >= 0.f) ? v.x : 0.2f * v.x;
    v.y = v.y * sc + sh; v.y = (v.y >= 0.f) ? v.y : 0.2f * v.y;
    v.z = v.z * sc + sh; v.z = (v.z >= 0.f) ? v.z : 0.2f * v.z;
    v.w = v.w * sc + sh; v.w = (v.w >= 0.f) ? v.w : 0.2f * v.w;
    x[i] = v;
}

// ---------------------------------------------------------------------------
// Minibatch discrimination + final reduction.
// ---------------------------------------------------------------------------
__global__ void pairwise_kernel()
{
    const int i = blockIdx.y, j = blockIdx.x, t = threadIdx.x;
    const float* a = g_c4 + (size_t)i * 16384;
    const float* b = g_c4 + (size_t)j * 16384;
    float s = 0.f;
    for (int k = t; k < 16384; k += 256) s += fabsf(a[k] - b[k]);
    __shared__ float sh[256];
    sh[t] = s;
    __syncthreads();
    for (int o = 128; o > 0; o >>= 1) {
        if (t < o) sh[t] += sh[t + o];
        __syncthreads();
    }
    if (t == 0)
        g_d[i * 32 + j] = sh[0] * (1.f / 16384.f) + ((i == j) ? 1e6f : 0.f);
}

__global__ void final_kernel(const float* __restrict__ w5, float* __restrict__ out)
{
    const int n = blockIdx.x, t = threadIdx.x;

    __shared__ float shm[256];
    shm[t] = (t < 32) ? g_d[n * 32 + t] : 1e30f;
    __syncthreads();
    for (int o = 128; o > 0; o >>= 1) {
        if (t < o) shm[t] = fminf(shm[t], shm[t + o]);
        __syncthreads();
    }
    const float s = shm[0];
    __syncthreads();

    double acc = 0.0;
    const float* h = g_c4 + (size_t)n * 16384;
    for (int k = t; k < 16384; k += 256)
        acc += (double)h[k] * (double)w5[k];
    if (t < 32)
        acc += (double)s * (double)w5[16384 + t];

    __shared__ double shd[256];
    shd[t] = acc;
    __syncthreads();
    for (int o = 128; o > 0; o >>= 1) {
        if (t < o) shd[t] += shd[t + o];
        __syncthreads();
    }
    if (t == 0) out[n] = (float)shd[0];
}

// ---------------------------------------------------------------------------
// Launch chain. Inputs: x, w1, w2, g2, b2, w3, g3, b3, w4, g4, b4, w5
// ---------------------------------------------------------------------------
extern "C" void kernel_launch(void* const* d_in, const int* in_sizes, int n_in,
                              void* d_out, int out_size)
{
    (void)in_sizes; (void)n_in; (void)out_size;
    const float* x  = (const float*)d_in[0];
    const float* w1 = (const float*)d_in[1];
    const float* w2 = (const float*)d_in[2];
    const float* g2 = (const float*)d_in[3];
    const float* b2 = (const float*)d_in[4];
    const float* w3 = (const float*)d_in[5];
    const float* g3 = (const float*)d_in[6];
    const float* b3 = (const float*)d_in[7];
    const float* w4 = (const float*)d_in[8];
    const float* g4 = (const float*)d_in[9];
    const float* b4 = (const float*)d_in[10];
    const float* w5 = (const float*)d_in[11];
    float* out = (float*)d_out;

    unsigned *h1p, *c2a, *c3a, *w2p, *w3p, *w4p;
    float *c2, *c3, *c3p, *c4, *c4p;
    cudaGetSymbolAddress((void**)&h1p, g_h1p);
    cudaGetSymbolAddress((void**)&c2,  g_c2);
    cudaGetSymbolAddress((void**)&c2a, g_c2a);
    cudaGetSymbolAddress((void**)&c3,  g_c3);
    cudaGetSymbolAddress((void**)&c3p, g_c3p);
    cudaGetSymbolAddress((void**)&c3a, g_c3a);
    cudaGetSymbolAddress((void**)&c4,  g_c4);
    cudaGetSymbolAddress((void**)&c4p, g_c4p);
    cudaGetSymbolAddress((void**)&w2p, g_w2p);
    cudaGetSymbolAddress((void**)&w3p, g_w3p);
    cudaGetSymbolAddress((void**)&w4p, g_w4p);

    // weight packing (independent of activations)
    packw_kernel<<<524288 / 256, 256>>>(w2, w2p, 524288);
    packw_kernel<<<2097152 / 256, 256>>>(w3, w3p, 2097152);
    packw_kernel<<<8388608 / 256, 256>>>(w4, w4p, 8388608);

    // L1
    conv1_kernel<<<dim3(16, 32), 1024>>>(x, w1);

    // L2: M=65536, N=128, K=4096
    convmma_kernel<<<dim3(512, 1, 1), 256>>>(h1p, w2p, c2,
        64, 128, 8, 16, 16, 16, 32, 32, 4096, 0);
    bn_stats_kernel<<<128, 256>>>(c2, g2, b2, 128, 2048);
    bn_pack_kernel<<<2097152 / 256, 256>>>((const float4*)c2, (uint4*)c2a,
                                           128, 512, 2097152);

    // L3: M=8192, N=256, K=8192, split-K=2
    convmma_kernel<<<dim3(64, 2, 2), 256>>>(c2a, w3p, c3p,
        128, 256, 4, 8, 8, 8, 16, 16, 4096, 2097152);
    reduce3_kernel<<<2097152 / 256, 256>>>();
    bn_stats_kernel<<<256, 256>>>(c3, g3, b3, 256, 256);
    bn_pack_kernel<<<524288 / 256, 256>>>((const float4*)c3, (uint4*)c3a,
                                          256, 64, 524288);

    // L4: M=1024, N=512, K=16384, split-K=4
    convmma_kernel<<<dim3(8, 4, 4), 256>>>(c3a, w4p, c4p,
        256, 512, 2, 4, 4, 4, 8, 8, 4096, 524288);
    reduce4_kernel<<<524288 / 256, 256>>>();
    bn_stats_kernel<<<512, 256>>>(c4, g4, b4, 512, 32);
    bn_lrelu_kernel<<<131072 / 256, 256>>>((float4*)c4, 512, 8, 131072);

    // minibatch discrimination + final
    pairwise_kernel<<<dim3(32, 32), 256>>>();
    final_kernel<<<32, 256>>>(w5, out);
}

// round 8
// speedup vs baseline: 2.2429x; 1.0320x over previous
#include <cuda_runtime.h>
#include <cuda_bf16.h>
#include <cstdint>

#define DEVFN __device__ __forceinline__

// ---------------------------------------------------------------------------
// Scratch (static device globals — no allocations anywhere)
// ---------------------------------------------------------------------------
__device__ unsigned g_h1p[33554432u];        // conv1 out, packed (bf16hi<<16|bf16lo)
__device__ float    g_c2 [8388608u];         // conv2 raw out (fp32, pre-BN)
__device__ unsigned g_c2a[8388608u];         // conv2 activated, packed
__device__ float    g_c3 [2097152u];
__device__ float    g_c3p[2u * 2097152u];    // conv3 split-K partials
__device__ unsigned g_c3a[2097152u];
__device__ float    g_c4 [524288u];
__device__ float    g_c4p[4u * 524288u];     // conv4 split-K partials
__device__ __nv_bfloat16 g_w2h[524288u],  g_w2l[524288u];   // pre-split weights
__device__ __nv_bfloat16 g_w3h[2097152u], g_w3l[2097152u];
__device__ __nv_bfloat16 g_w4h[8388608u], g_w4l[8388608u];
__device__ float    g_bnscale[512];
__device__ float    g_bnshift[512];
__device__ float    g_d[32 * 32];

// ---------------------------------------------------------------------------
// Helpers
// ---------------------------------------------------------------------------
DEVFN unsigned packhl(float v)
{
    __nv_bfloat16 h = __float2bfloat16(v);
    float r = v - __bfloat162float(h);
    __nv_bfloat16 l = __float2bfloat16(r);
    return ((unsigned)__bfloat16_as_ushort(h) << 16) |
           (unsigned)__bfloat16_as_ushort(l);
}

DEVFN uint32_t smem_u32(const void* p)
{
    uint32_t a;
    asm("{ .reg .u64 t; cvta.to.shared.u64 t, %1; cvt.u32.u64 %0, t; }"
        : "=r"(a) : "l"(p));
    return a;
}

DEVFN void ldsm4(uint32_t* r, uint32_t addr)
{
    asm volatile("ldmatrix.sync.aligned.m8n8.x4.shared.b16 {%0,%1,%2,%3}, [%4];"
                 : "=r"(r[0]), "=r"(r[1]), "=r"(r[2]), "=r"(r[3]) : "r"(addr));
}

DEVFN void mma16816(float* c, const uint32_t* a, uint32_t b0, uint32_t b1)
{
    asm volatile(
        "mma.sync.aligned.m16n8k16.row.col.f32.bf16.bf16.f32 "
        "{%0,%1,%2,%3}, {%4,%5,%6,%7}, {%8,%9}, {%0,%1,%2,%3};"
        : "+f"(c[0]), "+f"(c[1]), "+f"(c[2]), "+f"(c[3])
        : "r"(a[0]), "r"(a[1]), "r"(a[2]), "r"(a[3]), "r"(b0), "r"(b1));
}

DEVFN void cpa16(uint32_t dst, const void* src)
{
    asm volatile("cp.async.cg.shared.global [%0], [%1], 16;"
                 :: "r"(dst), "l"(src) : "memory");
}
#define CP_COMMIT() asm volatile("cp.async.commit_group;" ::: "memory")
#define CP_WAIT0()  asm volatile("cp.async.wait_group 0;" ::: "memory")

// ---------------------------------------------------------------------------
// Weight packer: fp32 -> separate hi/lo bf16 arrays
// ---------------------------------------------------------------------------
__global__ void packw2_kernel(const float* __restrict__ w,
                              __nv_bfloat16* __restrict__ oh,
                              __nv_bfloat16* __restrict__ ol, int n)
{
    const int i = blockIdx.x * 256 + threadIdx.x;
    if (i >= n) return;
    const float v = w[i];
    const __nv_bfloat16 h = __float2bfloat16(v);
    oh[i] = h;
    ol[i] = __float2bfloat16(v - __bfloat162float(h));
}

// ---------------------------------------------------------------------------
// Layer 1: conv3d (64,1,2,4,4), stride (2,2,2), pad (0,1,1), fused lrelu.
// Writes packed hi/lo bf16 u32 directly.
// ---------------------------------------------------------------------------
__global__ __launch_bounds__(1024, 1)
void conv1_kernel(const float* __restrict__ x, const float* __restrict__ w1)
{
    __shared__ float ws[64 * 32];
    const int t = threadIdx.x;
    for (int i = t; i < 2048; i += 1024) ws[i] = w1[i];
    __syncthreads();

    const int od = blockIdx.x;
    const int n  = blockIdx.y;
    const int oh = t >> 5;
    const int ow = t & 31;

    const float* xb = x + (size_t)n * 131072 + (size_t)(od * 2) * 4096;
    const int ih0 = oh * 2 - 1;
    const int iw0 = ow * 2 - 1;

    float v[32];
#pragma unroll
    for (int kd = 0; kd < 2; ++kd)
#pragma unroll
        for (int kh = 0; kh < 4; ++kh)
#pragma unroll
            for (int kw = 0; kw < 4; ++kw) {
                const int ih = ih0 + kh, iw = iw0 + kw;
                const bool ok = ((unsigned)ih < 64u) && ((unsigned)iw < 64u);
                v[kd * 16 + kh * 4 + kw] = ok ? xb[kd * 4096 + ih * 64 + iw] : 0.f;
            }

    unsigned* outb = g_h1p + ((size_t)(n * 64) * 16 + od) * 1024 + t;
#pragma unroll 4
    for (int c = 0; c < 64; ++c) {
        const float4* wp = (const float4*)&ws[c * 32];
        float acc = 0.f;
#pragma unroll
        for (int q = 0; q < 8; ++q) {
            const float4 w4 = wp[q];
            acc += v[q * 4 + 0] * w4.x + v[q * 4 + 1] * w4.y
                 + v[q * 4 + 2] * w4.z + v[q * 4 + 3] * w4.w;
        }
        acc = (acc >= 0.f) ? acc : 0.2f * acc;
        outb[(size_t)c * 16384] = packhl(acc);
    }
}

// ---------------------------------------------------------------------------
// mma.sync bf16 implicit-GEMM conv3d: kernel 4x4x4, stride 2, pad 1.
// D[M,N] = A[M,K]*B[N,K]^T, 3-term hi/lo split, fp32 accum.
// CTA 128x128, 8 warps (4x2), warp tile 32x64, K-chunk 32.
// DOUBLE-BUFFERED smem (one barrier/chunk); B via cp.async from pre-split
// hi/lo bf16 weight arrays; A via LDG gather + PRMT split + STS.
// Smem rows padded to PADK=40 bf16 (conflict-free ldmatrix).
// ---------------------------------------------------------------------------
#define PADK 40
#define TILEB (128 * PADK * 2)          // 10240 bytes per tile
#define BUFB  (4 * TILEB)               // Ah,Al,Bh,Bl per buffer
#define CM_SMEM (2 * BUFB)              // 81920 bytes

__global__ __launch_bounds__(256, 1)
void convmma_kernel(const unsigned* __restrict__ inp,
                    const __nv_bfloat16* __restrict__ wh,
                    const __nv_bfloat16* __restrict__ wl,
                    float* __restrict__ out,
                    int Cin, int Cout, int OD, int OH, int OW,
                    int ID, int IH, int IW,
                    int kPerSplit, int sliceElems)
{
    extern __shared__ unsigned char dsm[];
    const uint32_t smb = smem_u32(dsm);

    const int t    = threadIdx.x;
    const int lane = t & 31;
    const int wid  = t >> 5;
    const int mw   = (wid & 3) * 32;    // warp M offset in CTA tile
    const int nw   = (wid >> 2) * 64;   // warp N offset

    const int OHW  = OH * OW;
    const int ODHW = OD * OHW;
    const int IHW  = IH * IW;
    const int K    = Cin * 64;

    const int mBase = blockIdx.x * 128;
    const int cBase = blockIdx.y * 128;
    const int kBase = blockIdx.z * kPerSplit;

    // ---- loader state: thread = (row lm, 16-k half khf) ----
    const int lm   = t >> 1;
    const int khf  = t & 1;
    const int mload = mBase + lm;
    const int n_l = mload / ODHW;
    int srem = mload % ODHW;
    const int od = srem / OHW; srem %= OHW;
    const int oh = srem / OW;
    const int ow = srem % OW;
    const int id0 = od * 2 - 1;

    int hw16[16];
    unsigned okmask = 0;
#pragma unroll
    for (int j = 0; j < 16; ++j) {
        const int kh = j >> 2, kw = j & 3;
        const int ih = oh * 2 - 1 + kh;
        const int iw = ow * 2 - 1 + kw;
        const bool ok = ((unsigned)ih < (unsigned)IH) && ((unsigned)iw < (unsigned)IW);
        hw16[j] = ih * IW + iw;
        okmask |= (unsigned)ok << j;
    }

    const uint32_t stRow = (uint32_t)(lm * (PADK * 2) + khf * 32);  // byte offset
    const __nv_bfloat16* whRow = wh + (size_t)(cBase + lm) * K + kBase + khf * 16;
    const __nv_bfloat16* wlRow = wl + (size_t)(cBase + lm) * K + kBase + khf * 16;

    float acc[2][8][4];
#pragma unroll
    for (int a = 0; a < 2; ++a)
#pragma unroll
        for (int b = 0; b < 8; ++b)
#pragma unroll
            for (int q = 0; q < 4; ++q) acc[a][b][q] = 0.f;

    const int nCh = kPerSplit >> 5;

    unsigned va[16];
    auto gatherA = [&](int kc) {
        const int k0  = kBase + (kc << 5);
        const int cin = k0 >> 6;
        const int kd  = ((k0 >> 4) & 3) + khf;
        const int id  = id0 + kd;
        const bool okd = (unsigned)id < (unsigned)ID;
        const unsigned* bd = inp + (size_t)(n_l * Cin + cin) * ID * IHW
                           + (size_t)(okd ? id : 0) * IHW;
#pragma unroll
        for (int j = 0; j < 16; ++j)
            va[j] = (okd && ((okmask >> j) & 1)) ? bd[hw16[j]] : 0u;
    };

    auto cpasyncB = [&](int kc, int buf) {
        const uint32_t bh = smb + buf * BUFB + 2 * TILEB + stRow;
        const uint32_t bl = bh + TILEB;
        const size_t go = (size_t)(kc << 5);
        cpa16(bh,      whRow + go);
        cpa16(bh + 16, whRow + go + 8);
        cpa16(bl,      wlRow + go);
        cpa16(bl + 16, wlRow + go + 8);
        CP_COMMIT();
    };

    auto storeA = [&](int buf) {
        unsigned char* ah = dsm + buf * BUFB + stRow;
#pragma unroll
        for (int h = 0; h < 2; ++h) {
            uint4 ha, la;
            unsigned* hap = (unsigned*)&ha; unsigned* lap = (unsigned*)&la;
#pragma unroll
            for (int e = 0; e < 4; ++e) {
                const unsigned a0 = va[h * 8 + e * 2], a1 = va[h * 8 + e * 2 + 1];
                hap[e] = __byte_perm(a0, a1, 0x7632);
                lap[e] = __byte_perm(a0, a1, 0x5410);
            }
            *(uint4*)(ah + h * 16)          = ha;
            *(uint4*)(ah + TILEB + h * 16)  = la;
        }
    };

    // ---- prologue: fill buffer 0 ----
    gatherA(0);
    cpasyncB(0, 0);
    storeA(0);
    CP_WAIT0();
    __syncthreads();

    for (int kc = 0; kc < nCh; ++kc) {
        const int buf = kc & 1;
        const bool more = (kc + 1 < nCh);

        if (more) { gatherA(kc + 1); cpasyncB(kc + 1, buf ^ 1); }

        // ---- compute current buffer ----
        const uint32_t aB = smb + buf * BUFB;
        const uint32_t alB = aB + TILEB;
        const uint32_t bB = aB + 2 * TILEB;
        const uint32_t blB = aB + 3 * TILEB;
#pragma unroll
        for (int ks = 0; ks < 2; ++ks) {
            const uint32_t colb = (ks * 16 + 8 * (lane >> 4)) * 2;

            uint32_t ah[2][4], al[2][4];
#pragma unroll
            for (int tm = 0; tm < 2; ++tm) {
                const uint32_t ro = (uint32_t)(mw + tm * 16 + (lane & 15)) * (PADK * 2) + colb;
                ldsm4(ah[tm], aB + ro);
                ldsm4(al[tm], alB + ro);
            }
            uint32_t bh[4][4], bl[4][4];
#pragma unroll
            for (int tp = 0; tp < 4; ++tp) {
                const uint32_t ro = (uint32_t)(nw + tp * 16 + (lane & 15)) * (PADK * 2) + colb;
                ldsm4(bh[tp], bB + ro);
                ldsm4(bl[tp], blB + ro);
            }
#pragma unroll
            for (int tm = 0; tm < 2; ++tm)
#pragma unroll
                for (int tn = 0; tn < 8; ++tn) {
                    const int tp = tn >> 1, o = tn & 1;
                    mma16816(acc[tm][tn], ah[tm], bh[tp][o], bh[tp][o + 2]);
                    mma16816(acc[tm][tn], ah[tm], bl[tp][o], bl[tp][o + 2]);
                    mma16816(acc[tm][tn], al[tm], bh[tp][o], bh[tp][o + 2]);
                }
        }

        if (more) { storeA(buf ^ 1); CP_WAIT0(); }
        __syncthreads();
    }

    // ---- epilogue: fp32 NCDHW (per split slice) ----
    float* outz = out + (size_t)blockIdx.z * sliceElems;
#pragma unroll
    for (int tm = 0; tm < 2; ++tm) {
        const int m0 = mBase + mw + tm * 16 + (lane >> 2);
#pragma unroll
        for (int half = 0; half < 2; ++half) {
            const int m   = m0 + 8 * half;
            const int n_o = m / ODHW;
            const int s_o = m % ODHW;
            float* ob = outz + (size_t)(n_o * Cout + cBase) * ODHW + s_o;
#pragma unroll
            for (int tn = 0; tn < 8; ++tn) {
                const int col = nw + tn * 8 + 2 * (lane & 3);
                ob[(size_t)col * ODHW]       = acc[tm][tn][half * 2 + 0];
                ob[(size_t)(col + 1) * ODHW] = acc[tm][tn][half * 2 + 1];
            }
        }
    }
}

// ---------------------------------------------------------------------------
// Split-K reductions.
// ---------------------------------------------------------------------------
__global__ void reduce4_kernel()
{
    const int i = blockIdx.x * 256 + threadIdx.x;
    g_c4[i] = g_c4p[i] + g_c4p[i + 524288] + g_c4p[i + 2 * 524288]
            + g_c4p[i + 3 * 524288];
}

__global__ void reduce3_kernel()
{
    const int i = blockIdx.x * 256 + threadIdx.x;
    g_c3[i] = g_c3p[i] + g_c3p[i + 2097152];
}

// ---------------------------------------------------------------------------
// BatchNorm (training mode) statistics.
// ---------------------------------------------------------------------------
__global__ void bn_stats_kernel(const float* __restrict__ in,
                                const float* __restrict__ g,
                                const float* __restrict__ b,
                                int C, int ODHW)
{
    const int c = blockIdx.x;
    const int t = threadIdx.x;
    double s = 0.0, s2 = 0.0;
    for (int n = 0; n < 32; ++n) {
        const float* base = in + (size_t)(n * C + c) * ODHW;
        for (int sp = t; sp < ODHW; sp += 256) {
            const double v = (double)base[sp];
            s += v; s2 += v * v;
        }
    }
    __shared__ double sh[256], sh2[256];
    sh[t] = s; sh2[t] = s2;
    __syncthreads();
    for (int o = 128; o > 0; o >>= 1) {
        if (t < o) { sh[t] += sh[t + o]; sh2[t] += sh2[t + o]; }
        __syncthreads();
    }
    if (t == 0) {
        const double cnt  = 32.0 * (double)ODHW;
        const double mean = sh[0] / cnt;
        const double var  = sh2[0] / cnt - mean * mean;
        const double sc   = (double)g[c] / sqrt(var + 1e-5);
        g_bnscale[c] = (float)sc;
        g_bnshift[c] = (float)((double)b[c] - mean * sc);
    }
}

// ---------------------------------------------------------------------------
// BN apply + lrelu -> packed hi/lo u32 (for next conv's A).
// ---------------------------------------------------------------------------
__global__ void bn_pack_kernel(const float4* __restrict__ in, uint4* __restrict__ op,
                               int C, int ODHW4, int total4)
{
    const int i = blockIdx.x * 256 + threadIdx.x;
    if (i >= total4) return;
    const int c = (i / ODHW4) % C;
    const float sc = g_bnscale[c], sh = g_bnshift[c];
    float4 v = in[i];
    v.x = v.x * sc + sh; v.x = (v.x >= 0.f) ? v.x : 0.2f * v.x;
    v.y = v.y * sc + sh; v.y = (v.y >= 0.f) ? v.y : 0.2f * v.y;
    v.z = v.z * sc + sh; v.z = (v.z >= 0.f) ? v.z : 0.2f * v.z;
    v.w = v.w * sc + sh; v.w = (v.w >= 0.f) ? v.w : 0.2f * v.w;
    uint4 o;
    o.x = packhl(v.x); o.y = packhl(v.y); o.z = packhl(v.z); o.w = packhl(v.w);
    op[i] = o;
}

// ---------------------------------------------------------------------------
// BN apply + lrelu in place (fp32, conv4 output).
// ---------------------------------------------------------------------------
__global__ void bn_lrelu_kernel(float4* __restrict__ x, int C, int ODHW4, int total4)
{
    const int i = blockIdx.x * 256 + threadIdx.x;
    if (i >= total4) return;
    const int c = (i / ODHW4) % C;
    const float sc = g_bnscale[c], sh = g_bnshift[c];
    float4 v = x[i];
    v.x = v.x * sc + sh; v.x = (v.x >= 0.f) ? v.x : 0.2f * v.x;
    v.y = v.y * sc + sh; v.y = (v.y >= 0.f) ? v.y : 0.2f * v.y;
    v.z = v.z * sc + sh; v.z = (v.z >= 0.f) ? v.z : 0.2f * v.z;
    v.w = v.w * sc + sh; v.w = (v.w >= 0.f) ? v.w : 0.2f * v.w;
    x[i] = v;
}

// ---------------------------------------------------------------------------
// Minibatch discrimination + final reduction.
// ---------------------------------------------------------------------------
__global__ void pairwise_kernel()
{
    const int i = blockIdx.y, j = blockIdx.x, t = threadIdx.x;
    const float* a = g_c4 + (size_t)i * 16384;
    const float* b = g_c4 + (size_t)j * 16384;
    float s = 0.f;
    for (int k = t; k < 16384; k += 256) s += fabsf(a[k] - b[k]);
    __shared__ float sh[256];
    sh[t] = s;
    __syncthreads();
    for (int o = 128; o > 0; o >>= 1) {
        if (t < o) sh[t] += sh[t + o];
        __syncthreads();
    }
    if (t == 0)
        g_d[i * 32 + j] = sh[0] * (1.f / 16384.f) + ((i == j) ? 1e6f : 0.f);
}

__global__ void final_kernel(const float* __restrict__ w5, float* __restrict__ out)
{
    const int n = blockIdx.x, t = threadIdx.x;

    __shared__ float shm[256];
    shm[t] = (t < 32) ? g_d[n * 32 + t] : 1e30f;
    __syncthreads();
    for (int o = 128; o > 0; o >>= 1) {
        if (t < o) shm[t] = fminf(shm[t], shm[t + o]);
        __syncthreads();
    }
    const float s = shm[0];
    __syncthreads();

    double acc = 0.0;
    const float* h = g_c4 + (size_t)n * 16384;
    for (int k = t; k < 16384; k += 256)
        acc += (double)h[k] * (double)w5[k];
    if (t < 32)
        acc += (double)s * (double)w5[16384 + t];

    __shared__ double shd[256];
    shd[t] = acc;
    __syncthreads();
    for (int o = 128; o > 0; o >>= 1) {
        if (t < o) shd[t] += shd[t + o];
        __syncthreads();
    }
    if (t == 0) out[n] = (float)shd[0];
}

// ---------------------------------------------------------------------------
// Launch chain. Inputs: x, w1, w2, g2, b2, w3, g3, b3, w4, g4, b4, w5
// ---------------------------------------------------------------------------
extern "C" void kernel_launch(void* const* d_in, const int* in_sizes, int n_in,
                              void* d_out, int out_size)
{
    (void)in_sizes; (void)n_in; (void)out_size;
    const float* x  = (const float*)d_in[0];
    const float* w1 = (const float*)d_in[1];
    const float* w2 = (const float*)d_in[2];
    const float* g2 = (const float*)d_in[3];
    const float* b2 = (const float*)d_in[4];
    const float* w3 = (const float*)d_in[5];
    const float* g3 = (const float*)d_in[6];
    const float* b3 = (const float*)d_in[7];
    const float* w4 = (const float*)d_in[8];
    const float* g4 = (const float*)d_in[9];
    const float* b4 = (const float*)d_in[10];
    const float* w5 = (const float*)d_in[11];
    float* out = (float*)d_out;

    unsigned *h1p, *c2a, *c3a;
    float *c2, *c3, *c3p, *c4, *c4p;
    __nv_bfloat16 *w2h, *w2l, *w3h, *w3l, *w4h, *w4l;
    cudaGetSymbolAddress((void**)&h1p, g_h1p);
    cudaGetSymbolAddress((void**)&c2,  g_c2);
    cudaGetSymbolAddress((void**)&c2a, g_c2a);
    cudaGetSymbolAddress((void**)&c3,  g_c3);
    cudaGetSymbolAddress((void**)&c3p, g_c3p);
    cudaGetSymbolAddress((void**)&c3a, g_c3a);
    cudaGetSymbolAddress((void**)&c4,  g_c4);
    cudaGetSymbolAddress((void**)&c4p, g_c4p);
    cudaGetSymbolAddress((void**)&w2h, g_w2h);
    cudaGetSymbolAddress((void**)&w2l, g_w2l);
    cudaGetSymbolAddress((void**)&w3h, g_w3h);
    cudaGetSymbolAddress((void**)&w3l, g_w3l);
    cudaGetSymbolAddress((void**)&w4h, g_w4h);
    cudaGetSymbolAddress((void**)&w4l, g_w4l);

    cudaFuncSetAttribute(convmma_kernel,
                         cudaFuncAttributeMaxDynamicSharedMemorySize, CM_SMEM);

    // weight packing (independent of activations)
    packw2_kernel<<<524288 / 256, 256>>>(w2, w2h, w2l, 524288);
    packw2_kernel<<<2097152 / 256, 256>>>(w3, w3h, w3l, 2097152);
    packw2_kernel<<<8388608 / 256, 256>>>(w4, w4h, w4l, 8388608);

    // L1
    conv1_kernel<<<dim3(16, 32), 1024>>>(x, w1);

    // L2: M=65536, N=128, K=4096
    convmma_kernel<<<dim3(512, 1, 1), 256, CM_SMEM>>>(h1p, w2h, w2l, c2,
        64, 128, 8, 16, 16, 16, 32, 32, 4096, 0);
    bn_stats_kernel<<<128, 256>>>(c2, g2, b2, 128, 2048);
    bn_pack_kernel<<<2097152 / 256, 256>>>((const float4*)c2, (uint4*)c2a,
                                           128, 512, 2097152);

    // L3: M=8192, N=256, K=8192, split-K=2
    convmma_kernel<<<dim3(64, 2, 2), 256, CM_SMEM>>>(c2a, w3h, w3l, c3p,
        128, 256, 4, 8, 8, 8, 16, 16, 4096, 2097152);
    reduce3_kernel<<<2097152 / 256, 256>>>();
    bn_stats_kernel<<<256, 256>>>(c3, g3, b3, 256, 256);
    bn_pack_kernel<<<524288 / 256, 256>>>((const float4*)c3, (uint4*)c3a,
                                          256, 64, 524288);

    // L4: M=1024, N=512, K=16384, split-K=4
    convmma_kernel<<<dim3(8, 4, 4), 256, CM_SMEM>>>(c3a, w4h, w4l, c4p,
        256, 512, 2, 4, 4, 4, 8, 8, 4096, 524288);
    reduce4_kernel<<<524288 / 256, 256>>>();
    bn_stats_kernel<<<512, 256>>>(c4, g4, b4, 512, 32);
    bn_lrelu_kernel<<<131072 / 256, 256>>>((float4*)c4, 512, 8, 131072);

    // minibatch discrimination + final
    pairwise_kernel<<<dim3(32, 32), 256>>>();
    final_kernel<<<32, 256>>>(w5, out);
}

// round 9
// speedup vs baseline: 2.7717x; 1.2358x over previous
#include <cuda_runtime.h>
#include <cstdint>

#define DEVFN __device__ __forceinline__

// ---------------------------------------------------------------------------
// Scratch (static device globals — no allocations anywhere)
// ---------------------------------------------------------------------------
__device__ float          g_h1 [33554432u];     // conv1 out fp32
__device__ unsigned short g_h1q[33554432u];     // quantized (hi8<<8 | lo8)
__device__ float          g_c2 [8388608u];      // conv2 raw out
__device__ unsigned short g_c2q[8388608u];
__device__ float          g_c3 [2097152u];
__device__ float          g_c3p[2u * 2097152u];
__device__ unsigned short g_c3q[2097152u];
__device__ float          g_c4 [524288u];
__device__ float          g_c4p[8u * 524288u];
__device__ signed char    g_w2h[524288u],  g_w2l[524288u];
__device__ signed char    g_w3h[2097152u], g_w3l[2097152u];
__device__ signed char    g_w4h[8388608u], g_w4l[8388608u];
__device__ int            g_amax[8];            // float bits, all values >= 0
__device__ float          g_bnscale[512];
__device__ float          g_bnshift[512];
__device__ float          g_d[32 * 32];

#define QMAX 32512.0f

// ---------------------------------------------------------------------------
// Helpers
// ---------------------------------------------------------------------------
DEVFN uint32_t smem_u32(const void* p)
{
    uint32_t a;
    asm("{ .reg .u64 t; cvta.to.shared.u64 t, %1; cvt.u32.u64 %0, t; }"
        : "=r"(a) : "l"(p));
    return a;
}

DEVFN void ldsm4(uint32_t* r, uint32_t addr)
{
    asm volatile("ldmatrix.sync.aligned.m8n8.x4.shared.b16 {%0,%1,%2,%3}, [%4];"
                 : "=r"(r[0]), "=r"(r[1]), "=r"(r[2]), "=r"(r[3]) : "r"(addr));
}

DEVFN void imma(int* c, const uint32_t* a, uint32_t b0, uint32_t b1)
{
    asm volatile(
        "mma.sync.aligned.m16n8k32.row.col.s32.s8.s8.s32 "
        "{%0,%1,%2,%3}, {%4,%5,%6,%7}, {%8,%9}, {%0,%1,%2,%3};"
        : "+r"(c[0]), "+r"(c[1]), "+r"(c[2]), "+r"(c[3])
        : "r"(a[0]), "r"(a[1]), "r"(a[2]), "r"(a[3]), "r"(b0), "r"(b1));
}

DEVFN void cpa16(uint32_t dst, const void* src)
{
    asm volatile("cp.async.cg.shared.global [%0], [%1], 16;"
                 :: "r"(dst), "l"(src) : "memory");
}
#define CP_COMMIT() asm volatile("cp.async.commit_group;" ::: "memory")
#define CP_WAIT0()  asm volatile("cp.async.wait_group 0;" ::: "memory")

DEVFN void amax_atomic(int idx, float v)
{
    atomicMax(&g_amax[idx], __float_as_int(v));
}

DEVFN unsigned short quant16(float v, float inv)
{
    float q = rintf(v * inv);
    q = fminf(fmaxf(q, -QMAX), QMAX);
    const int Q = (int)q;
    const int h = (Q + 128) >> 8;          // round-half-up, h in [-127,127]
    const int l = Q - (h << 8);            // l in [-128,127]
    return (unsigned short)(((h & 0xff) << 8) | (l & 0xff));
}

// ---------------------------------------------------------------------------
// Small setup kernels
// ---------------------------------------------------------------------------
__global__ void zeroamax_kernel()
{
    if (threadIdx.x < 8) g_amax[threadIdx.x] = 0;
}

__global__ void wamax_kernel(const float* __restrict__ w, int n, int idx)
{
    const int stride = gridDim.x * 256;
    float am = 0.f;
    for (int i = blockIdx.x * 256 + threadIdx.x; i < n; i += stride)
        am = fmaxf(am, fabsf(w[i]));
    __shared__ float sh[256];
    sh[threadIdx.x] = am;
    __syncthreads();
    for (int o = 128; o > 0; o >>= 1) {
        if (threadIdx.x < o) sh[threadIdx.x] = fmaxf(sh[threadIdx.x], sh[threadIdx.x + o]);
        __syncthreads();
    }
    if (threadIdx.x == 0) amax_atomic(idx, sh[0]);
}

__global__ void wquant_kernel(const float* __restrict__ w,
                              signed char* __restrict__ oh,
                              signed char* __restrict__ ol, int n, int idx)
{
    const int i = blockIdx.x * 256 + threadIdx.x;
    if (i >= n) return;
    const float amax = __int_as_float(g_amax[idx]);
    const float inv = QMAX / fmaxf(amax, 1e-30f);
    const unsigned short q = quant16(w[i], inv);
    oh[i] = (signed char)(q >> 8);
    ol[i] = (signed char)(q & 0xff);
}

// generic fp32 -> u16 quantizer (for h1)
__global__ void quantA_kernel(const float* __restrict__ in,
                              unsigned short* __restrict__ o, int n, int idx)
{
    const int i = blockIdx.x * 256 + threadIdx.x;
    if (i >= n) return;
    const float amax = __int_as_float(g_amax[idx]);
    const float inv = QMAX / fmaxf(amax, 1e-30f);
    o[i] = quant16(in[i], inv);
}

// ---------------------------------------------------------------------------
// Layer 1: conv3d (64,1,2,4,4), stride (2,2,2), pad (0,1,1), fused lrelu.
// Writes fp32 + tracks tensor amax (for later quantization).
// ---------------------------------------------------------------------------
__global__ __launch_bounds__(1024, 1)
void conv1_kernel(const float* __restrict__ x, const float* __restrict__ w1)
{
    __shared__ float ws[64 * 32];
    const int t = threadIdx.x;
    for (int i = t; i < 2048; i += 1024) ws[i] = w1[i];
    __syncthreads();

    const int od = blockIdx.x;
    const int n  = blockIdx.y;
    const int oh = t >> 5;
    const int ow = t & 31;

    const float* xb = x + (size_t)n * 131072 + (size_t)(od * 2) * 4096;
    const int ih0 = oh * 2 - 1;
    const int iw0 = ow * 2 - 1;

    float v[32];
#pragma unroll
    for (int kd = 0; kd < 2; ++kd)
#pragma unroll
        for (int kh = 0; kh < 4; ++kh)
#pragma unroll
            for (int kw = 0; kw < 4; ++kw) {
                const int ih = ih0 + kh, iw = iw0 + kw;
                const bool ok = ((unsigned)ih < 64u) && ((unsigned)iw < 64u);
                v[kd * 16 + kh * 4 + kw] = ok ? xb[kd * 4096 + ih * 64 + iw] : 0.f;
            }

    float* outb = g_h1 + ((size_t)(n * 64) * 16 + od) * 1024 + t;
    float am = 0.f;
#pragma unroll 4
    for (int c = 0; c < 64; ++c) {
        const float4* wp = (const float4*)&ws[c * 32];
        float acc = 0.f;
#pragma unroll
        for (int q = 0; q < 8; ++q) {
            const float4 w4 = wp[q];
            acc += v[q * 4 + 0] * w4.x + v[q * 4 + 1] * w4.y
                 + v[q * 4 + 2] * w4.z + v[q * 4 + 3] * w4.w;
        }
        acc = (acc >= 0.f) ? acc : 0.2f * acc;
        am = fmaxf(am, fabsf(acc));
        outb[(size_t)c * 16384] = acc;
    }

    __shared__ float sm[1024];
    sm[t] = am;
    __syncthreads();
    for (int o = 512; o > 0; o >>= 1) {
        if (t < o) sm[t] = fmaxf(sm[t], sm[t + o]);
        __syncthreads();
    }
    if (t == 0) amax_atomic(0, sm[0]);
}

// ---------------------------------------------------------------------------
// int8 IMMA implicit-GEMM conv3d: kernel 4x4x4, stride 2, pad 1.
// D = sA*sB*(65536*Ah.Bh + 256*(Ah.Bl + Al.Bh)); s32 accumulation.
// CTA 128x128, 16 warps (4x4 grid), warp tile 32x32, K-chunk 32 int8.
// A: u16 (hi<<8|lo) NCDHW gather + PRMT split; B: cp.async pre-split s8.
// Smem rows 32B data + 16B pad (48B): conflict-free ldmatrix.
// ---------------------------------------------------------------------------
#define ROWB 48
#define TILE (128 * ROWB)     // 6144 B
#define BUF  (4 * TILE)       // Ah, Al, Bh, Bl
#define CI_SMEM (2 * BUF)     // 49152 B

__global__ __launch_bounds__(512, 1)
void convimma_kernel(const unsigned short* __restrict__ inq,
                     const signed char* __restrict__ wh,
                     const signed char* __restrict__ wl,
                     float* __restrict__ out,
                     int Cin, int Cout, int OD, int OH, int OW,
                     int ID, int IH, int IW,
                     int kPerSplit, int sliceElems, int iaIdx, int ibIdx)
{
    extern __shared__ unsigned char dsm[];
    const uint32_t smb = smem_u32(dsm);

    const int t    = threadIdx.x;
    const int lane = t & 31;
    const int wid  = t >> 5;
    const int mw   = (wid & 3) * 32;     // warp M offset
    const int nww  = (wid >> 2) * 32;    // warp N offset

    const int OHW  = OH * OW;
    const int ODHW = OD * OHW;
    const int IHW  = IH * IW;
    const int K    = Cin * 64;

    const int mBase = blockIdx.x * 128;
    const int cBase = blockIdx.y * 128;
    const int kBase = blockIdx.z * kPerSplit;

    // ---- A loader state: thread = (row lm, k-quarter kq of 8) ----
    const int lm = t >> 2;          // 0..127
    const int kq = t & 3;           // 8 k-elements each
    const int mload = mBase + lm;
    const int n_l = mload / ODHW;
    int srem = mload % ODHW;
    const int od = srem / OHW; srem %= OHW;
    const int oh = srem / OW;
    const int ow = srem % OW;
    const int id0 = od * 2 - 1;
    const int kdq = kq >> 1;        // extra kd within chunk
    const int khb = (kq & 1) * 2;   // kh base for this quarter

    int hw8[8];
    unsigned ok8 = 0;
#pragma unroll
    for (int j = 0; j < 8; ++j) {
        const int kh = khb + (j >> 2);
        const int kw = j & 3;
        const int ih = oh * 2 - 1 + kh;
        const int iw = ow * 2 - 1 + kw;
        const bool ok = ((unsigned)ih < (unsigned)IH) && ((unsigned)iw < (unsigned)IW);
        hw8[j] = ih * IW + iw;
        ok8 |= (unsigned)ok << j;
    }
    const uint32_t aOff = (uint32_t)(lm * ROWB + kq * 8);

    // ---- B loader: thread -> one 16B cp.async ----
    const int bidx  = t >> 1;
    const int brow  = bidx & 127;
    const int bpl   = bidx >> 7;          // 0 = hi, 1 = lo
    const int bhalf = t & 1;
    const signed char* wsrc = (bpl ? wl : wh) + (size_t)(cBase + brow) * K
                            + kBase + bhalf * 16;
    const uint32_t bDst = (uint32_t)((2 + bpl) * TILE + brow * ROWB + bhalf * 16);

    // ---- ldmatrix lane addressing ----
    const uint32_t lrow = (lane & 15);
    const uint32_t lsel = (lane >> 4) * 16;

    int acc_hh[2][4][4], acc_md[2][4][4];
#pragma unroll
    for (int a = 0; a < 2; ++a)
#pragma unroll
        for (int b = 0; b < 4; ++b)
#pragma unroll
            for (int q = 0; q < 4; ++q) { acc_hh[a][b][q] = 0; acc_md[a][b][q] = 0; }

    const int nCh = kPerSplit >> 5;

    unsigned va[8];
    auto gatherA = [&](int kc) {
        const int k0  = kBase + (kc << 5);
        const int cin = k0 >> 6;
        const int kd  = ((k0 >> 4) & 3) + kdq;
        const int id  = id0 + kd;
        const bool okd = (unsigned)id < (unsigned)ID;
        const unsigned short* bd = inq + ((size_t)(n_l * Cin + cin) * ID
                                          + (okd ? id : 0)) * IHW;
#pragma unroll
        for (int j = 0; j < 8; ++j)
            va[j] = (okd && ((ok8 >> j) & 1)) ? (unsigned)bd[hw8[j]] : 0u;
    };

    auto cpasyncB = [&](int kc, int buf) {
        cpa16(smb + buf * BUF + bDst, wsrc + (kc << 5));
        CP_COMMIT();
    };

    auto storeA = [&](int buf) {
        unsigned char* base = dsm + buf * BUF + aOff;
        uint32_t hi0, hi1, lo0, lo1, t01, t23;
        t01 = __byte_perm(va[0], va[1], 0x0051);
        t23 = __byte_perm(va[2], va[3], 0x5100);
        hi0 = __byte_perm(t01, t23, 0x7610);
        t01 = __byte_perm(va[4], va[5], 0x0051);
        t23 = __byte_perm(va[6], va[7], 0x5100);
        hi1 = __byte_perm(t01, t23, 0x7610);
        t01 = __byte_perm(va[0], va[1], 0x0040);
        t23 = __byte_perm(va[2], va[3], 0x4000);
        lo0 = __byte_perm(t01, t23, 0x7610);
        t01 = __byte_perm(va[4], va[5], 0x0040);
        t23 = __byte_perm(va[6], va[7], 0x4000);
        lo1 = __byte_perm(t01, t23, 0x7610);
        *(uint2*)(base)        = make_uint2(hi0, hi1);
        *(uint2*)(base + TILE) = make_uint2(lo0, lo1);
    };

    // ---- prologue ----
    gatherA(0);
    cpasyncB(0, 0);
    storeA(0);
    CP_WAIT0();
    __syncthreads();

    for (int kc = 0; kc < nCh; ++kc) {
        const int buf = kc & 1;
        const bool more = (kc + 1 < nCh);

        if (more) { gatherA(kc + 1); cpasyncB(kc + 1, buf ^ 1); }

        const uint32_t aH = smb + buf * BUF;
        const uint32_t aL = aH + TILE;
        const uint32_t bH = aH + 2 * TILE;
        const uint32_t bL = aH + 3 * TILE;

        uint32_t ah[2][4], al[2][4], bh[2][4], bl[2][4];
#pragma unroll
        for (int tm = 0; tm < 2; ++tm) {
            const uint32_t ro = (uint32_t)(mw + tm * 16 + lrow) * ROWB + lsel;
            ldsm4(ah[tm], aH + ro);
            ldsm4(al[tm], aL + ro);
        }
#pragma unroll
        for (int bt = 0; bt < 2; ++bt) {
            const uint32_t ro = (uint32_t)(nww + bt * 16 + lrow) * ROWB + lsel;
            ldsm4(bh[bt], bH + ro);
            ldsm4(bl[bt], bL + ro);
        }

#pragma unroll
        for (int tm = 0; tm < 2; ++tm)
#pragma unroll
            for (int bt = 0; bt < 2; ++bt)
#pragma unroll
                for (int sub = 0; sub < 2; ++sub) {
                    const int tn = bt * 2 + sub;
                    imma(acc_hh[tm][tn], ah[tm], bh[bt][sub], bh[bt][sub + 2]);
                    imma(acc_md[tm][tn], ah[tm], bl[bt][sub], bl[bt][sub + 2]);
                    imma(acc_md[tm][tn], al[tm], bh[bt][sub], bh[bt][sub + 2]);
                }

        if (more) { storeA(buf ^ 1); CP_WAIT0(); }
        __syncthreads();
    }

    // ---- epilogue ----
    const float amA = __int_as_float(g_amax[iaIdx]);
    const float amB = __int_as_float(g_amax[ibIdx]);
    const float sAB = (amA / QMAX) * (amB / QMAX);

    float* outz = out + (size_t)blockIdx.z * sliceElems;
#pragma unroll
    for (int tm = 0; tm < 2; ++tm) {
#pragma unroll
        for (int half = 0; half < 2; ++half) {
            const int m   = mBase + mw + tm * 16 + (lane >> 2) + 8 * half;
            const int n_o = m / ODHW;
            const int s_o = m % ODHW;
            float* ob = outz + (size_t)(n_o * Cout + cBase) * ODHW + s_o;
#pragma unroll
            for (int tn = 0; tn < 4; ++tn) {
                const int col = nww + tn * 8 + 2 * (lane & 3);
                const float v0 = sAB * fmaf(65536.f,
                    (float)acc_hh[tm][tn][half * 2 + 0],
                    256.f * (float)acc_md[tm][tn][half * 2 + 0]);
                const float v1 = sAB * fmaf(65536.f,
                    (float)acc_hh[tm][tn][half * 2 + 1],
                    256.f * (float)acc_md[tm][tn][half * 2 + 1]);
                ob[(size_t)col * ODHW]       = v0;
                ob[(size_t)(col + 1) * ODHW] = v1;
            }
        }
    }
}

// ---------------------------------------------------------------------------
// Split-K reductions.
// ---------------------------------------------------------------------------
__global__ void reduce8_kernel()
{
    const int i = blockIdx.x * 256 + threadIdx.x;
    float s = 0.f;
#pragma unroll
    for (int z = 0; z < 8; ++z) s += g_c4p[i + (size_t)z * 524288];
    g_c4[i] = s;
}

__global__ void reduce3_kernel()
{
    const int i = blockIdx.x * 256 + threadIdx.x;
    g_c3[i] = g_c3p[i] + g_c3p[i + 2097152];
}

// ---------------------------------------------------------------------------
// BatchNorm stats (+ optional amax sweep of the activated output).
// ---------------------------------------------------------------------------
__global__ void bn_stats_kernel(const float* __restrict__ in,
                                const float* __restrict__ g,
                                const float* __restrict__ b,
                                int C, int ODHW, int amaxIdx)
{
    const int c = blockIdx.x;
    const int t = threadIdx.x;
    double s = 0.0, s2 = 0.0;
    for (int n = 0; n < 32; ++n) {
        const float* base = in + (size_t)(n * C + c) * ODHW;
        for (int sp = t; sp < ODHW; sp += 256) {
            const double v = (double)base[sp];
            s += v; s2 += v * v;
        }
    }
    __shared__ double sh[256], sh2[256];
    __shared__ float s_sc, s_sh;
    sh[t] = s; sh2[t] = s2;
    __syncthreads();
    for (int o = 128; o > 0; o >>= 1) {
        if (t < o) { sh[t] += sh[t + o]; sh2[t] += sh2[t + o]; }
        __syncthreads();
    }
    if (t == 0) {
        const double cnt  = 32.0 * (double)ODHW;
        const double mean = sh[0] / cnt;
        const double var  = sh2[0] / cnt - mean * mean;
        const double sc   = (double)g[c] / sqrt(var + 1e-5);
        g_bnscale[c] = (float)sc;
        g_bnshift[c] = (float)((double)b[c] - mean * sc);
        s_sc = (float)sc;
        s_sh = (float)((double)b[c] - mean * sc);
    }
    __syncthreads();

    if (amaxIdx >= 0) {
        const float sc = s_sc, shv = s_sh;
        float am = 0.f;
        for (int n = 0; n < 32; ++n) {
            const float* base = in + (size_t)(n * C + c) * ODHW;
            for (int sp = t; sp < ODHW; sp += 256) {
                float v = base[sp] * sc + shv;
                v = (v >= 0.f) ? v : 0.2f * v;
                am = fmaxf(am, fabsf(v));
            }
        }
        __shared__ float shm[256];
        shm[t] = am;
        __syncthreads();
        for (int o = 128; o > 0; o >>= 1) {
            if (t < o) shm[t] = fmaxf(shm[t], shm[t + o]);
            __syncthreads();
        }
        if (t == 0) amax_atomic(amaxIdx, shm[0]);
    }
}

// ---------------------------------------------------------------------------
// BN apply + lrelu -> quantized u16 (for next conv's A).
// ---------------------------------------------------------------------------
__global__ void quantBN_kernel(const float* __restrict__ in,
                               unsigned short* __restrict__ o,
                               int C, int ODHW, int total, int amaxIdx)
{
    const int i = blockIdx.x * 256 + threadIdx.x;
    if (i >= total) return;
    const int c = (i / ODHW) % C;
    float v = in[i] * g_bnscale[c] + g_bnshift[c];
    v = (v >= 0.f) ? v : 0.2f * v;
    const float amax = __int_as_float(g_amax[amaxIdx]);
    o[i] = quant16(v, QMAX / fmaxf(amax, 1e-30f));
}

// ---------------------------------------------------------------------------
// BN apply + lrelu in place (fp32, conv4 output).
// ---------------------------------------------------------------------------
__global__ void bn_lrelu_kernel(float4* __restrict__ x, int C, int ODHW4, int total4)
{
    const int i = blockIdx.x * 256 + threadIdx.x;
    if (i >= total4) return;
    const int c = (i / ODHW4) % C;
    const float sc = g_bnscale[c], sh = g_bnshift[c];
    float4 v = x[i];
    v.x = v.x * sc + sh; v.x = (v.x >= 0.f) ? v.x : 0.2f * v.x;
    v.y = v.y * sc + sh; v.y = (v.y >= 0.f) ? v.y : 0.2f * v.y;
    v.z = v.z * sc + sh; v.z = (v.z >= 0.f) ? v.z : 0.2f * v.z;
    v.w = v.w * sc + sh; v.w = (v.w >= 0.f) ? v.w : 0.2f * v.w;
    x[i] = v;
}

// ---------------------------------------------------------------------------
// Minibatch discrimination + final reduction.
// ---------------------------------------------------------------------------
__global__ void pairwise_kernel()
{
    const int i = blockIdx.y, j = blockIdx.x, t = threadIdx.x;
    const float* a = g_c4 + (size_t)i * 16384;
    const float* b = g_c4 + (size_t)j * 16384;
    float s = 0.f;
    for (int k = t; k < 16384; k += 256) s += fabsf(a[k] - b[k]);
    __shared__ float sh[256];
    sh[t] = s;
    __syncthreads();
    for (int o = 128; o > 0; o >>= 1) {
        if (t < o) sh[t] += sh[t + o];
        __syncthreads();
    }
    if (t == 0)
        g_d[i * 32 + j] = sh[0] * (1.f / 16384.f) + ((i == j) ? 1e6f : 0.f);
}

__global__ void final_kernel(const float* __restrict__ w5, float* __restrict__ out)
{
    const int n = blockIdx.x, t = threadIdx.x;

    __shared__ float shm[256];
    shm[t] = (t < 32) ? g_d[n * 32 + t] : 1e30f;
    __syncthreads();
    for (int o = 128; o > 0; o >>= 1) {
        if (t < o) shm[t] = fminf(shm[t], shm[t + o]);
        __syncthreads();
    }
    const float s = shm[0];
    __syncthreads();

    double acc = 0.0;
    const float* h = g_c4 + (size_t)n * 16384;
    for (int k = t; k < 16384; k += 256)
        acc += (double)h[k] * (double)w5[k];
    if (t < 32)
        acc += (double)s * (double)w5[16384 + t];

    __shared__ double shd[256];
    shd[t] = acc;
    __syncthreads();
    for (int o = 128; o > 0; o >>= 1) {
        if (t < o) shd[t] += shd[t + o];
        __syncthreads();
    }
    if (t == 0) out[n] = (float)shd[0];
}

// ---------------------------------------------------------------------------
// Launch chain. Inputs: x, w1, w2, g2, b2, w3, g3, b3, w4, g4, b4, w5
// ---------------------------------------------------------------------------
extern "C" void kernel_launch(void* const* d_in, const int* in_sizes, int n_in,
                              void* d_out, int out_size)
{
    (void)in_sizes; (void)n_in; (void)out_size;
    const float* x  = (const float*)d_in[0];
    const float* w1 = (const float*)d_in[1];
    const float* w2 = (const float*)d_in[2];
    const float* g2 = (const float*)d_in[3];
    const float* b2 = (const float*)d_in[4];
    const float* w3 = (const float*)d_in[5];
    const float* g3 = (const float*)d_in[6];
    const float* b3 = (const float*)d_in[7];
    const float* w4 = (const float*)d_in[8];
    const float* g4 = (const float*)d_in[9];
    const float* b4 = (const float*)d_in[10];
    const float* w5 = (const float*)d_in[11];
    float* out = (float*)d_out;

    float *h1, *c2, *c3, *c3p, *c4, *c4p;
    unsigned short *h1q, *c2q, *c3q;
    signed char *w2h, *w2l, *w3h, *w3l, *w4h, *w4l;
    cudaGetSymbolAddress((void**)&h1,  g_h1);
    cudaGetSymbolAddress((void**)&h1q, g_h1q);
    cudaGetSymbolAddress((void**)&c2,  g_c2);
    cudaGetSymbolAddress((void**)&c2q, g_c2q);
    cudaGetSymbolAddress((void**)&c3,  g_c3);
    cudaGetSymbolAddress((void**)&c3p, g_c3p);
    cudaGetSymbolAddress((void**)&c3q, g_c3q);
    cudaGetSymbolAddress((void**)&c4,  g_c4);
    cudaGetSymbolAddress((void**)&c4p, g_c4p);
    cudaGetSymbolAddress((void**)&w2h, g_w2h);
    cudaGetSymbolAddress((void**)&w2l, g_w2l);
    cudaGetSymbolAddress((void**)&w3h, g_w3h);
    cudaGetSymbolAddress((void**)&w3l, g_w3l);
    cudaGetSymbolAddress((void**)&w4h, g_w4h);
    cudaGetSymbolAddress((void**)&w4l, g_w4l);

    cudaFuncSetAttribute(convimma_kernel,
                         cudaFuncAttributeMaxDynamicSharedMemorySize, CI_SMEM);

    // amax init + weight quantization
    zeroamax_kernel<<<1, 32>>>();
    wamax_kernel<<<256, 256>>>(w2, 524288, 1);
    wamax_kernel<<<256, 256>>>(w3, 2097152, 3);
    wamax_kernel<<<256, 256>>>(w4, 8388608, 5);
    wquant_kernel<<<524288 / 256, 256>>>(w2, w2h, w2l, 524288, 1);
    wquant_kernel<<<2097152 / 256, 256>>>(w3, w3h, w3l, 2097152, 3);
    wquant_kernel<<<8388608 / 256, 256>>>(w4, w4h, w4l, 8388608, 5);

    // L1 + quantize
    conv1_kernel<<<dim3(16, 32), 1024>>>(x, w1);
    quantA_kernel<<<33554432 / 256, 256>>>(h1, h1q, 33554432, 0);

    // L2: M=65536, N=128, K=4096
    convimma_kernel<<<dim3(512, 1, 1), 512, CI_SMEM>>>(h1q, w2h, w2l, c2,
        64, 128, 8, 16, 16, 16, 32, 32, 4096, 0, 0, 1);
    bn_stats_kernel<<<128, 256>>>(c2, g2, b2, 128, 2048, 2);
    quantBN_kernel<<<8388608 / 256, 256>>>(c2, c2q, 128, 2048, 8388608, 2);

    // L3: M=8192, N=256, K=8192, split-K=2
    convimma_kernel<<<dim3(64, 2, 2), 512, CI_SMEM>>>(c2q, w3h, w3l, c3p,
        128, 256, 4, 8, 8, 8, 16, 16, 4096, 2097152, 2, 3);
    reduce3_kernel<<<2097152 / 256, 256>>>();
    bn_stats_kernel<<<256, 256>>>(c3, g3, b3, 256, 256, 4);
    quantBN_kernel<<<2097152 / 256, 256>>>(c3, c3q, 256, 256, 2097152, 4);

    // L4: M=1024, N=512, K=16384, split-K=8
    convimma_kernel<<<dim3(8, 4, 8), 512, CI_SMEM>>>(c3q, w4h, w4l, c4p,
        256, 512, 2, 4, 4, 4, 8, 8, 2048, 524288, 4, 5);
    reduce8_kernel<<<524288 / 256, 256>>>();
    bn_stats_kernel<<<512, 256>>>(c4, g4, b4, 512, 32, -1);
    bn_lrelu_kernel<<<131072 / 256, 256>>>((float4*)c4, 512, 8, 131072);

    // minibatch discrimination + final
    pairwise_kernel<<<dim3(32, 32), 256>>>();
    final_kernel<<<32, 256>>>(w5, out);
}

// round 11
// speedup vs baseline: 2.9441x; 1.0622x over previous
#include <cuda_runtime.h>
#include <cstdint>

#define DEVFN __device__ __forceinline__

// ---------------------------------------------------------------------------
// Scratch (static device globals — no allocations anywhere)
// ---------------------------------------------------------------------------
__device__ float          g_h1 [33554432u];     // conv1 out fp32
__device__ unsigned short g_h1q[33554432u];     // quantized (hi8<<8 | lo8)
__device__ float          g_c2 [8388608u];      // conv2 raw out
__device__ unsigned short g_c2q[8388608u];
__device__ float          g_c3 [2097152u];
__device__ float          g_c3p[2u * 2097152u];
__device__ unsigned short g_c3q[2097152u];
__device__ float          g_c4 [524288u];
__device__ float          g_c4p[8u * 524288u];
__device__ signed char    g_w2h[524288u],  g_w2l[524288u];
__device__ signed char    g_w3h[2097152u], g_w3l[2097152u];
__device__ signed char    g_w4h[8388608u], g_w4l[8388608u];
__device__ int            g_amax[8];            // float bits, all values >= 0
__device__ float          g_bnscale[512];
__device__ float          g_bnshift[512];
__device__ float          g_d[32 * 32];

#define QMAX 32512.0f

// ---------------------------------------------------------------------------
// Helpers
// ---------------------------------------------------------------------------
DEVFN uint32_t smem_u32(const void* p)
{
    uint32_t a;
    asm("{ .reg .u64 t; cvta.to.shared.u64 t, %1; cvt.u32.u64 %0, t; }"
        : "=r"(a) : "l"(p));
    return a;
}

DEVFN void ldsm4(uint32_t* r, uint32_t addr)
{
    asm volatile("ldmatrix.sync.aligned.m8n8.x4.shared.b16 {%0,%1,%2,%3}, [%4];"
                 : "=r"(r[0]), "=r"(r[1]), "=r"(r[2]), "=r"(r[3]) : "r"(addr));
}

DEVFN void imma(int* c, const uint32_t* a, uint32_t b0, uint32_t b1)
{
    asm volatile(
        "mma.sync.aligned.m16n8k32.row.col.s32.s8.s8.s32 "
        "{%0,%1,%2,%3}, {%4,%5,%6,%7}, {%8,%9}, {%0,%1,%2,%3};"
        : "+r"(c[0]), "+r"(c[1]), "+r"(c[2]), "+r"(c[3])
        : "r"(a[0]), "r"(a[1]), "r"(a[2]), "r"(a[3]), "r"(b0), "r"(b1));
}

DEVFN void cpa16(uint32_t dst, const void* src)
{
    asm volatile("cp.async.cg.shared.global [%0], [%1], 16;"
                 :: "r"(dst), "l"(src) : "memory");
}
#define CP_COMMIT() asm volatile("cp.async.commit_group;" ::: "memory")

DEVFN void amax_atomic(int idx, float v)
{
    atomicMax(&g_amax[idx], __float_as_int(v));
}

DEVFN unsigned short quant16(float v, float inv)
{
    float q = rintf(v * inv);
    q = fminf(fmaxf(q, -QMAX), QMAX);
    const int Q = (int)q;
    const int h = (Q + 128) >> 8;          // round-half-up, h in [-127,127]
    const int l = Q - (h << 8);            // l in [-128,127]
    return (unsigned short)(((h & 0xff) << 8) | (l & 0xff));
}

// ---------------------------------------------------------------------------
// Small setup kernels
// ---------------------------------------------------------------------------
__global__ void zeroamax_kernel()
{
    if (threadIdx.x < 8) g_amax[threadIdx.x] = 0;
}

__global__ void wamax_kernel(const float4* __restrict__ w, int n4, int idx)
{
    const int stride = gridDim.x * 256;
    float am = 0.f;
    for (int i = blockIdx.x * 256 + threadIdx.x; i < n4; i += stride) {
        const float4 v = w[i];
        am = fmaxf(am, fmaxf(fmaxf(fabsf(v.x), fabsf(v.y)),
                             fmaxf(fabsf(v.z), fabsf(v.w))));
    }
    __shared__ float sh[256];
    sh[threadIdx.x] = am;
    __syncthreads();
    for (int o = 128; o > 0; o >>= 1) {
        if (threadIdx.x < o) sh[threadIdx.x] = fmaxf(sh[threadIdx.x], sh[threadIdx.x + o]);
        __syncthreads();
    }
    if (threadIdx.x == 0) amax_atomic(idx, sh[0]);
}

__global__ void wquant_kernel(const float* __restrict__ w,
                              signed char* __restrict__ oh,
                              signed char* __restrict__ ol, int n, int idx)
{
    const int i = blockIdx.x * 256 + threadIdx.x;
    if (i >= n) return;
    const float amax = __int_as_float(g_amax[idx]);
    const float inv = QMAX / fmaxf(amax, 1e-30f);
    const unsigned short q = quant16(w[i], inv);
    oh[i] = (signed char)(q >> 8);
    ol[i] = (signed char)(q & 0xff);
}

// fp32 -> u16 quantizer, 8 elements per thread
__global__ void quantA_kernel(const float4* __restrict__ in,
                              uint4* __restrict__ o, int n8, int idx)
{
    const int i = blockIdx.x * 256 + threadIdx.x;
    if (i >= n8) return;
    const float amax = __int_as_float(g_amax[idx]);
    const float inv = QMAX / fmaxf(amax, 1e-30f);
    const float4 a = in[2 * i];
    const float4 b = in[2 * i + 1];
    uint4 r;
    r.x = (unsigned)quant16(a.x, inv) | ((unsigned)quant16(a.y, inv) << 16);
    r.y = (unsigned)quant16(a.z, inv) | ((unsigned)quant16(a.w, inv) << 16);
    r.z = (unsigned)quant16(b.x, inv) | ((unsigned)quant16(b.y, inv) << 16);
    r.w = (unsigned)quant16(b.z, inv) | ((unsigned)quant16(b.w, inv) << 16);
    o[i] = r;
}

// ---------------------------------------------------------------------------
// Layer 1: conv3d (64,1,2,4,4), stride (2,2,2), pad (0,1,1), fused lrelu.
// Writes fp32 + tracks tensor amax (for later quantization).
// ---------------------------------------------------------------------------
__global__ __launch_bounds__(1024, 1)
void conv1_kernel(const float* __restrict__ x, const float* __restrict__ w1)
{
    __shared__ float ws[64 * 32];
    const int t = threadIdx.x;
    for (int i = t; i < 2048; i += 1024) ws[i] = w1[i];
    __syncthreads();

    const int od = blockIdx.x;
    const int n  = blockIdx.y;
    const int oh = t >> 5;
    const int ow = t & 31;

    const float* xb = x + (size_t)n * 131072 + (size_t)(od * 2) * 4096;
    const int ih0 = oh * 2 - 1;
    const int iw0 = ow * 2 - 1;

    float v[32];
#pragma unroll
    for (int kd = 0; kd < 2; ++kd)
#pragma unroll
        for (int kh = 0; kh < 4; ++kh)
#pragma unroll
            for (int kw = 0; kw < 4; ++kw) {
                const int ih = ih0 + kh, iw = iw0 + kw;
                const bool ok = ((unsigned)ih < 64u) && ((unsigned)iw < 64u);
                v[kd * 16 + kh * 4 + kw] = ok ? xb[kd * 4096 + ih * 64 + iw] : 0.f;
            }

    float* outb = g_h1 + ((size_t)(n * 64) * 16 + od) * 1024 + t;
    float am = 0.f;
#pragma unroll 4
    for (int c = 0; c < 64; ++c) {
        const float4* wp = (const float4*)&ws[c * 32];
        float acc = 0.f;
#pragma unroll
        for (int q = 0; q < 8; ++q) {
            const float4 w4 = wp[q];
            acc += v[q * 4 + 0] * w4.x + v[q * 4 + 1] * w4.y
                 + v[q * 4 + 2] * w4.z + v[q * 4 + 3] * w4.w;
        }
        acc = (acc >= 0.f) ? acc : 0.2f * acc;
        am = fmaxf(am, fabsf(acc));
        outb[(size_t)c * 16384] = acc;
    }

    __shared__ float sm[1024];
    sm[t] = am;
    __syncthreads();
    for (int o = 512; o > 0; o >>= 1) {
        if (t < o) sm[t] = fmaxf(sm[t], sm[t + o]);
        __syncthreads();
    }
    if (t == 0) amax_atomic(0, sm[0]);
}

// ---------------------------------------------------------------------------
// int8 IMMA implicit-GEMM conv3d: kernel 4x4x4, stride 2, pad 1.
// D = sA*sB*(65536*Ah.Bh + 256*(Ah.Bl + Al.Bh)); s32 accumulation.
// CTA 128x128, 16 warps (4x4), warp tile 32x32, K-chunk 32 int8.
// THREE-stage pipeline, CUTLASS ordering: wait_group -> barrier -> issue
// prefetch(kc+2) -> compute(kc) -> storeA(kc+2). ONE barrier per chunk;
// the barrier sits AFTER the wait so every thread's cp.async data is
// visible before any ldmatrix (R10's bug: barrier before wait).
// Smem rows 32B data + 16B pad (48B): conflict-free ldmatrix.
// ---------------------------------------------------------------------------
#define ROWB 48
#define TILE (128 * ROWB)     // 6144 B
#define BUF  (4 * TILE)       // Ah, Al, Bh, Bl
#define CI_SMEM (3 * BUF)     // 73728 B

__global__ __launch_bounds__(512, 1)
void convimma_kernel(const unsigned short* __restrict__ inq,
                     const signed char* __restrict__ wh,
                     const signed char* __restrict__ wl,
                     float* __restrict__ out,
                     int Cin, int Cout, int OD, int OH, int OW,
                     int ID, int IH, int IW,
                     int kPerSplit, int sliceElems, int iaIdx, int ibIdx)
{
    extern __shared__ unsigned char dsm[];
    const uint32_t smb = smem_u32(dsm);

    const int t    = threadIdx.x;
    const int lane = t & 31;
    const int wid  = t >> 5;
    const int mw   = (wid & 3) * 32;     // warp M offset
    const int nww  = (wid >> 2) * 32;    // warp N offset

    const int OHW  = OH * OW;
    const int ODHW = OD * OHW;
    const int IHW  = IH * IW;
    const int K    = Cin * 64;

    const int mBase = blockIdx.x * 128;
    const int cBase = blockIdx.y * 128;
    const int kBase = blockIdx.z * kPerSplit;

    // ---- A loader state: thread = (row lm, k-quarter kq of 8) ----
    const int lm = t >> 2;          // 0..127
    const int kq = t & 3;           // 8 k-elements each
    const int mload = mBase + lm;
    const int n_l = mload / ODHW;
    int srem = mload % ODHW;
    const int od = srem / OHW; srem %= OHW;
    const int oh = srem / OW;
    const int ow = srem % OW;
    const int id0 = od * 2 - 1;
    const int kdq = kq >> 1;        // extra kd within chunk
    const int khb = (kq & 1) * 2;   // kh base for this quarter

    int hw8[8];
    unsigned ok8 = 0;
#pragma unroll
    for (int j = 0; j < 8; ++j) {
        const int kh = khb + (j >> 2);
        const int kw = j & 3;
        const int ih = oh * 2 - 1 + kh;
        const int iw = ow * 2 - 1 + kw;
        const bool ok = ((unsigned)ih < (unsigned)IH) && ((unsigned)iw < (unsigned)IW);
        hw8[j] = ih * IW + iw;
        ok8 |= (unsigned)ok << j;
    }
    const uint32_t aOff = (uint32_t)(lm * ROWB + kq * 8);

    // ---- B loader: thread -> one 16B cp.async ----
    const int bidx  = t >> 1;
    const int brow  = bidx & 127;
    const int bpl   = bidx >> 7;          // 0 = hi, 1 = lo
    const int bhalf = t & 1;
    const signed char* wsrc = (bpl ? wl : wh) + (size_t)(cBase + brow) * K
                            + kBase + bhalf * 16;
    const uint32_t bDst = (uint32_t)((2 + bpl) * TILE + brow * ROWB + bhalf * 16);

    // ---- ldmatrix lane addressing ----
    const uint32_t lrow = (lane & 15);
    const uint32_t lsel = (lane >> 4) * 16;

    int acc_hh[2][4][4], acc_md[2][4][4];
#pragma unroll
    for (int a = 0; a < 2; ++a)
#pragma unroll
        for (int b = 0; b < 4; ++b)
#pragma unroll
            for (int q = 0; q < 4; ++q) { acc_hh[a][b][q] = 0; acc_md[a][b][q] = 0; }

    const int nCh = kPerSplit >> 5;

    unsigned va[8];
    auto gatherA = [&](int kc) {
        const int k0  = kBase + (kc << 5);
        const int cin = k0 >> 6;
        const int kd  = ((k0 >> 4) & 3) + kdq;
        const int id  = id0 + kd;
        const bool okd = (unsigned)id < (unsigned)ID;
        const unsigned short* bd = inq + ((size_t)(n_l * Cin + cin) * ID
                                          + (okd ? id : 0)) * IHW;
#pragma unroll
        for (int j = 0; j < 8; ++j)
            va[j] = (okd && ((ok8 >> j) & 1)) ? (unsigned)bd[hw8[j]] : 0u;
    };

    auto cpasyncB = [&](int kc, int buf) {
        cpa16(smb + buf * BUF + bDst, wsrc + (kc << 5));
        CP_COMMIT();
    };

    auto storeA = [&](int buf) {
        unsigned char* base = dsm + buf * BUF + aOff;
        uint32_t hi0, hi1, lo0, lo1, t01, t23;
        t01 = __byte_perm(va[0], va[1], 0x0051);
        t23 = __byte_perm(va[2], va[3], 0x5100);
        hi0 = __byte_perm(t01, t23, 0x7610);
        t01 = __byte_perm(va[4], va[5], 0x0051);
        t23 = __byte_perm(va[6], va[7], 0x5100);
        hi1 = __byte_perm(t01, t23, 0x7610);
        t01 = __byte_perm(va[0], va[1], 0x0040);
        t23 = __byte_perm(va[2], va[3], 0x4000);
        lo0 = __byte_perm(t01, t23, 0x7610);
        t01 = __byte_perm(va[4], va[5], 0x0040);
        t23 = __byte_perm(va[6], va[7], 0x4000);
        lo1 = __byte_perm(t01, t23, 0x7610);
        *(uint2*)(base)        = make_uint2(hi0, hi1);
        *(uint2*)(base + TILE) = make_uint2(lo0, lo1);
    };

    // ---- prologue: fill buffers 0 and 1 ----
    gatherA(0);
    cpasyncB(0, 0);
    storeA(0);
    gatherA(1);
    cpasyncB(1, 1);
    storeA(1);

    for (int kc = 0; kc < nCh; ++kc) {
        const int pf = kc + 2;

        // wait for OWN B(kc) copies (newest committed group is B(kc+1)),
        // THEN barrier: makes every thread's copies + storeA visible, and
        // retires compute(kc-1) so buffer (kc+2)%3 is free for refill.
        if (kc + 1 < nCh)
            asm volatile("cp.async.wait_group 1;" ::: "memory");
        else
            asm volatile("cp.async.wait_group 0;" ::: "memory");
        __syncthreads();

        if (pf < nCh) { cpasyncB(pf, pf % 3); gatherA(pf); }

        // ---- compute buffer kc%3 ----
        const uint32_t aH = smb + (kc % 3) * BUF;
        const uint32_t aL = aH + TILE;
        const uint32_t bH = aH + 2 * TILE;
        const uint32_t bL = aH + 3 * TILE;

        uint32_t ah[2][4], al[2][4], bh[2][4], bl[2][4];
#pragma unroll
        for (int tm = 0; tm < 2; ++tm) {
            const uint32_t ro = (uint32_t)(mw + tm * 16 + lrow) * ROWB + lsel;
            ldsm4(ah[tm], aH + ro);
            ldsm4(al[tm], aL + ro);
        }
#pragma unroll
        for (int bt = 0; bt < 2; ++bt) {
            const uint32_t ro = (uint32_t)(nww + bt * 16 + lrow) * ROWB + lsel;
            ldsm4(bh[bt], bH + ro);
            ldsm4(bl[bt], bL + ro);
        }

#pragma unroll
        for (int tm = 0; tm < 2; ++tm)
#pragma unroll
            for (int bt = 0; bt < 2; ++bt)
#pragma unroll
                for (int sub = 0; sub < 2; ++sub) {
                    const int tn = bt * 2 + sub;
                    imma(acc_hh[tm][tn], ah[tm], bh[bt][sub], bh[bt][sub + 2]);
                    imma(acc_md[tm][tn], ah[tm], bl[bt][sub], bl[bt][sub + 2]);
                    imma(acc_md[tm][tn], al[tm], bh[bt][sub], bh[bt][sub + 2]);
                }

        if (pf < nCh) storeA(pf % 3);
    }

    // ---- epilogue ----
    const float amA = __int_as_float(g_amax[iaIdx]);
    const float amB = __int_as_float(g_amax[ibIdx]);
    const float sAB = (amA / QMAX) * (amB / QMAX);

    float* outz = out + (size_t)blockIdx.z * sliceElems;
#pragma unroll
    for (int tm = 0; tm < 2; ++tm) {
#pragma unroll
        for (int half = 0; half < 2; ++half) {
            const int m   = mBase + mw + tm * 16 + (lane >> 2) + 8 * half;
            const int n_o = m / ODHW;
            const int s_o = m % ODHW;
            float* ob = outz + (size_t)(n_o * Cout + cBase) * ODHW + s_o;
#pragma unroll
            for (int tn = 0; tn < 4; ++tn) {
                const int col = nww + tn * 8 + 2 * (lane & 3);
                const float v0 = sAB * fmaf(65536.f,
                    (float)acc_hh[tm][tn][half * 2 + 0],
                    256.f * (float)acc_md[tm][tn][half * 2 + 0]);
                const float v1 = sAB * fmaf(65536.f,
                    (float)acc_hh[tm][tn][half * 2 + 1],
                    256.f * (float)acc_md[tm][tn][half * 2 + 1]);
                ob[(size_t)col * ODHW]       = v0;
                ob[(size_t)(col + 1) * ODHW] = v1;
            }
        }
    }
}

// ---------------------------------------------------------------------------
// Split-K reductions.
// ---------------------------------------------------------------------------
__global__ void reduce8_kernel()
{
    const int i = blockIdx.x * 256 + threadIdx.x;
    float s = 0.f;
#pragma unroll
    for (int z = 0; z < 8; ++z) s += g_c4p[i + (size_t)z * 524288];
    g_c4[i] = s;
}

__global__ void reduce3_kernel()
{
    const int i = blockIdx.x * 256 + threadIdx.x;
    g_c3[i] = g_c3p[i] + g_c3p[i + 2097152];
}

// ---------------------------------------------------------------------------
// BatchNorm stats (+ optional amax sweep of the activated output).
// ---------------------------------------------------------------------------
__global__ void bn_stats_kernel(const float* __restrict__ in,
                                const float* __restrict__ g,
                                const float* __restrict__ b,
                                int C, int ODHW, int amaxIdx)
{
    const int c = blockIdx.x;
    const int t = threadIdx.x;
    double s = 0.0, s2 = 0.0;
    for (int n = 0; n < 32; ++n) {
        const float* base = in + (size_t)(n * C + c) * ODHW;
        for (int sp = t; sp < ODHW; sp += 256) {
            const double v = (double)base[sp];
            s += v; s2 += v * v;
        }
    }
    __shared__ double sh[256], sh2[256];
    __shared__ float s_sc, s_sh;
    sh[t] = s; sh2[t] = s2;
    __syncthreads();
    for (int o = 128; o > 0; o >>= 1) {
        if (t < o) { sh[t] += sh[t + o]; sh2[t] += sh2[t + o]; }
        __syncthreads();
    }
    if (t == 0) {
        const double cnt  = 32.0 * (double)ODHW;
        const double mean = sh[0] / cnt;
        const double var  = sh2[0] / cnt - mean * mean;
        const double sc   = (double)g[c] / sqrt(var + 1e-5);
        g_bnscale[c] = (float)sc;
        g_bnshift[c] = (float)((double)b[c] - mean * sc);
        s_sc = (float)sc;
        s_sh = (float)((double)b[c] - mean * sc);
    }
    __syncthreads();

    if (amaxIdx >= 0) {
        const float sc = s_sc, shv = s_sh;
        float am = 0.f;
        for (int n = 0; n < 32; ++n) {
            const float* base = in + (size_t)(n * C + c) * ODHW;
            for (int sp = t; sp < ODHW; sp += 256) {
                float v = base[sp] * sc + shv;
                v = (v >= 0.f) ? v : 0.2f * v;
                am = fmaxf(am, fabsf(v));
            }
        }
        __shared__ float shm[256];
        shm[t] = am;
        __syncthreads();
        for (int o = 128; o > 0; o >>= 1) {
            if (t < o) shm[t] = fmaxf(shm[t], shm[t + o]);
            __syncthreads();
        }
        if (t == 0) amax_atomic(amaxIdx, shm[0]);
    }
}

// ---------------------------------------------------------------------------
// BN apply + lrelu -> quantized u16, 4 elements per thread.
// ---------------------------------------------------------------------------
__global__ void quantBN_kernel(const float4* __restrict__ in,
                               uint2* __restrict__ o,
                               int C, int ODHW, int total4, int amaxIdx)
{
    const int i = blockIdx.x * 256 + threadIdx.x;
    if (i >= total4) return;
    const int c = ((i * 4) / ODHW) % C;     // ODHW % 4 == 0
    const float sc = g_bnscale[c], sh = g_bnshift[c];
    const float amax = __int_as_float(g_amax[amaxIdx]);
    const float inv = QMAX / fmaxf(amax, 1e-30f);
    float4 v = in[i];
    v.x = v.x * sc + sh; v.x = (v.x >= 0.f) ? v.x : 0.2f * v.x;
    v.y = v.y * sc + sh; v.y = (v.y >= 0.f) ? v.y : 0.2f * v.y;
    v.z = v.z * sc + sh; v.z = (v.z >= 0.f) ? v.z : 0.2f * v.z;
    v.w = v.w * sc + sh; v.w = (v.w >= 0.f) ? v.w : 0.2f * v.w;
    uint2 r;
    r.x = (unsigned)quant16(v.x, inv) | ((unsigned)quant16(v.y, inv) << 16);
    r.y = (unsigned)quant16(v.z, inv) | ((unsigned)quant16(v.w, inv) << 16);
    o[i] = r;
}

// ---------------------------------------------------------------------------
// BN apply + lrelu in place (fp32, conv4 output).
// ---------------------------------------------------------------------------
__global__ void bn_lrelu_kernel(float4* __restrict__ x, int C, int ODHW4, int total4)
{
    const int i = blockIdx.x * 256 + threadIdx.x;
    if (i >= total4) return;
    const int c = (i / ODHW4) % C;
    const float sc = g_bnscale[c], sh = g_bnshift[c];
    float4 v = x[i];
    v.x = v.x * sc + sh; v.x = (v.x >= 0.f) ? v.x : 0.2f * v.x;
    v.y = v.y * sc + sh; v.y = (v.y >= 0.f) ? v.y : 0.2f * v.y;
    v.z = v.z * sc + sh; v.z = (v.z >= 0.f) ? v.z : 0.2f * v.z;
    v.w = v.w * sc + sh; v.w = (v.w >= 0.f) ? v.w : 0.2f * v.w;
    x[i] = v;
}

// ---------------------------------------------------------------------------
// Minibatch discrimination + final reduction.
// ---------------------------------------------------------------------------
__global__ void pairwise_kernel()
{
    const int i = blockIdx.y, j = blockIdx.x, t = threadIdx.x;
    const float* a = g_c4 + (size_t)i * 16384;
    const float* b = g_c4 + (size_t)j * 16384;
    float s = 0.f;
    for (int k = t; k < 16384; k += 256) s += fabsf(a[k] - b[k]);
    __shared__ float sh[256];
    sh[t] = s;
    __syncthreads();
    for (int o = 128; o > 0; o >>= 1) {
        if (t < o) sh[t] += sh[t + o];
        __syncthreads();
    }
    if (t == 0)
        g_d[i * 32 + j] = sh[0] * (1.f / 16384.f) + ((i == j) ? 1e6f : 0.f);
}

__global__ void final_kernel(const float* __restrict__ w5, float* __restrict__ out)
{
    const int n = blockIdx.x, t = threadIdx.x;

    __shared__ float shm[256];
    shm[t] = (t < 32) ? g_d[n * 32 + t] : 1e30f;
    __syncthreads();
    for (int o = 128; o > 0; o >>= 1) {
        if (t < o) shm[t] = fminf(shm[t], shm[t + o]);
        __syncthreads();
    }
    const float s = shm[0];
    __syncthreads();

    double acc = 0.0;
    const float* h = g_c4 + (size_t)n * 16384;
    for (int k = t; k < 16384; k += 256)
        acc += (double)h[k] * (double)w5[k];
    if (t < 32)
        acc += (double)s * (double)w5[16384 + t];

    __shared__ double shd[256];
    shd[t] = acc;
    __syncthreads();
    for (int o = 128; o > 0; o >>= 1) {
        if (t < o) shd[t] += shd[t + o];
        __syncthreads();
    }
    if (t == 0) out[n] = (float)shd[0];
}

// ---------------------------------------------------------------------------
// Launch chain. Inputs: x, w1, w2, g2, b2, w3, g3, b3, w4, g4, b4, w5
// ---------------------------------------------------------------------------
extern "C" void kernel_launch(void* const* d_in, const int* in_sizes, int n_in,
                              void* d_out, int out_size)
{
    (void)in_sizes; (void)n_in; (void)out_size;
    const float* x  = (const float*)d_in[0];
    const float* w1 = (const float*)d_in[1];
    const float* w2 = (const float*)d_in[2];
    const float* g2 = (const float*)d_in[3];
    const float* b2 = (const float*)d_in[4];
    const float* w3 = (const float*)d_in[5];
    const float* g3 = (const float*)d_in[6];
    const float* b3 = (const float*)d_in[7];
    const float* w4 = (const float*)d_in[8];
    const float* g4 = (const float*)d_in[9];
    const float* b4 = (const float*)d_in[10];
    const float* w5 = (const float*)d_in[11];
    float* out = (float*)d_out;

    float *h1, *c2, *c3, *c3p, *c4, *c4p;
    unsigned short *h1q, *c2q, *c3q;
    signed char *w2h, *w2l, *w3h, *w3l, *w4h, *w4l;
    cudaGetSymbolAddress((void**)&h1,  g_h1);
    cudaGetSymbolAddress((void**)&h1q, g_h1q);
    cudaGetSymbolAddress((void**)&c2,  g_c2);
    cudaGetSymbolAddress((void**)&c2q, g_c2q);
    cudaGetSymbolAddress((void**)&c3,  g_c3);
    cudaGetSymbolAddress((void**)&c3p, g_c3p);
    cudaGetSymbolAddress((void**)&c3q, g_c3q);
    cudaGetSymbolAddress((void**)&c4,  g_c4);
    cudaGetSymbolAddress((void**)&c4p, g_c4p);
    cudaGetSymbolAddress((void**)&w2h, g_w2h);
    cudaGetSymbolAddress((void**)&w2l, g_w2l);
    cudaGetSymbolAddress((void**)&w3h, g_w3h);
    cudaGetSymbolAddress((void**)&w3l, g_w3l);
    cudaGetSymbolAddress((void**)&w4h, g_w4h);
    cudaGetSymbolAddress((void**)&w4l, g_w4l);

    cudaFuncSetAttribute(convimma_kernel,
                         cudaFuncAttributeMaxDynamicSharedMemorySize, CI_SMEM);

    // amax init + weight quantization
    zeroamax_kernel<<<1, 32>>>();
    wamax_kernel<<<512, 256>>>((const float4*)w2, 524288 / 4, 1);
    wamax_kernel<<<512, 256>>>((const float4*)w3, 2097152 / 4, 3);
    wamax_kernel<<<512, 256>>>((const float4*)w4, 8388608 / 4, 5);
    wquant_kernel<<<524288 / 256, 256>>>(w2, w2h, w2l, 524288, 1);
    wquant_kernel<<<2097152 / 256, 256>>>(w3, w3h, w3l, 2097152, 3);
    wquant_kernel<<<8388608 / 256, 256>>>(w4, w4h, w4l, 8388608, 5);

    // L1 + quantize
    conv1_kernel<<<dim3(16, 32), 1024>>>(x, w1);
    quantA_kernel<<<(33554432 / 8) / 256, 256>>>((const float4*)h1, (uint4*)h1q,
                                                 33554432 / 8, 0);

    // L2: M=65536, N=128, K=4096
    convimma_kernel<<<dim3(512, 1, 1), 512, CI_SMEM>>>(h1q, w2h, w2l, c2,
        64, 128, 8, 16, 16, 16, 32, 32, 4096, 0, 0, 1);
    bn_stats_kernel<<<128, 256>>>(c2, g2, b2, 128, 2048, 2);
    quantBN_kernel<<<(8388608 / 4) / 256, 256>>>((const float4*)c2, (uint2*)c2q,
                                                 128, 2048, 8388608 / 4, 2);

    // L3: M=8192, N=256, K=8192, split-K=2
    convimma_kernel<<<dim3(64, 2, 2), 512, CI_SMEM>>>(c2q, w3h, w3l, c3p,
        128, 256, 4, 8, 8, 8, 16, 16, 4096, 2097152, 2, 3);
    reduce3_kernel<<<2097152 / 256, 256>>>();
    bn_stats_kernel<<<256, 256>>>(c3, g3, b3, 256, 256, 4);
    quantBN_kernel<<<(2097152 / 4) / 256, 256>>>((const float4*)c3, (uint2*)c3q,
                                                 256, 256, 2097152 / 4, 4);

    // L4: M=1024, N=512, K=16384, split-K=8
    convimma_kernel<<<dim3(8, 4, 8), 512, CI_SMEM>>>(c3q, w4h, w4l, c4p,
        256, 512, 2, 4, 4, 4, 8, 8, 2048, 524288, 4, 5);
    reduce8_kernel<<<524288 / 256, 256>>>();
    bn_stats_kernel<<<512, 256>>>(c4, g4, b4, 512, 32, -1);
    bn_lrelu_kernel<<<131072 / 256, 256>>>((float4*)c4, 512, 8, 131072);

    // minibatch discrimination + final
    pairwise_kernel<<<dim3(32, 32), 256>>>();
    final_kernel<<<32, 256>>>(w5, out);
}